// round 2
// baseline (speedup 1.0000x reference)
#include <cuda_runtime.h>

#define CIN   128
#define HW    96
#define HWSZ  (HW*HW)      // 9216
#define BATCH 4
#define OC1   128
#define OC2   108
#define NDG   4

// ---------------- scratch (static device globals; no allocs) ----------------
__device__ float g_xres[BATCH * OC1 * HWSZ];   // conv1 output
__device__ float g_co  [BATCH * OC2 * HWSZ];   // conv2 output
__device__ float g_w1t [CIN * 9 * OC1];        // weights transposed [ic][k][oc]
__device__ float g_w2t [CIN * 9 * OC2];
__device__ float g_wdt [CIN * 9 * OC1];

// ---------------- packed f32x2 helpers ----------------
__device__ __forceinline__ unsigned long long pack2(float lo, float hi) {
    unsigned long long r;
    asm("mov.b64 %0, {%1, %2};" : "=l"(r) : "f"(lo), "f"(hi));
    return r;
}
__device__ __forceinline__ void unpack2(unsigned long long v, float& lo, float& hi) {
    asm("mov.b64 {%0, %1}, %2;" : "=f"(lo), "=f"(hi) : "l"(v));
}
__device__ __forceinline__ unsigned long long ffma2(unsigned long long a,
                                                    unsigned long long b,
                                                    unsigned long long c) {
    unsigned long long d;
    asm("fma.rn.f32x2 %0, %1, %2, %3;" : "=l"(d) : "l"(a), "l"(b), "l"(c));
    return d;
}

// ---------------- weight transpose: dst[ic][k][oc] = src[oc][ic][k] ----------------
__global__ void transpose_w_kernel(const float* __restrict__ src, int OC, int which) {
    float* dst = (which == 0) ? g_w1t : (which == 1) ? g_w2t : g_wdt;
    int i = blockIdx.x * 256 + threadIdx.x;
    int total = OC * CIN * 9;
    if (i >= total) return;
    int oc  = i / (CIN * 9);
    int rem = i % (CIN * 9);
    int ic  = rem / 9;
    int k   = rem % 9;
    dst[(ic * 9 + k) * OC + oc] = src[i];
}

// ---------------- conv3x3, pad=1, NCHW ----------------
// Block: 256 threads = 8 oc-groups (8 oc each, as 4 f32x2 pairs) x 32 px-threads.
// Spatial tile 32x8; each px-thread owns 8 consecutive columns of one row.
// Per ic: pack each input value ONCE (v2[10] per kernel row), reuse across
// dc and px -> 288 FFMA2 out of ~384 issued instructions.
template<int OC, int MODE>
__global__ __launch_bounds__(256, 2) void conv3x3_kernel(const float* __restrict__ xin,
                                                         const float* __restrict__ bias) {
    const float* x  = (MODE == 0) ? xin : g_xres;
    const float* wt = (MODE == 0) ? g_w1t : g_w2t;
    float*       y  = (MODE == 0) ? g_xres : g_co;

    const int tid    = threadIdx.x;
    const int b      = blockIdx.y;
    const int ocb    = blockIdx.z;                 // 64 oc per block
    const int tile_x = (blockIdx.x % 3) * 32;
    const int tile_y = (blockIdx.x / 3) * 8;
    const int oc_grp = tid >> 5;                   // 0..7 -> 8 oc each
    const int pt     = tid & 31;
    const int ty     = pt >> 2;                    // 0..7  (row)
    const int txq    = pt & 3;                     // 0..3  (8 cols each)

    __shared__ float in_s[8 * 10 * 34];                  // [ic][r(10)][c(34)]
    __shared__ __align__(8) float sw[8 * 9 * 64];        // [ic][k][oc_l(64)]

    unsigned long long acc[8][4];
#pragma unroll
    for (int i = 0; i < 8; i++)
#pragma unroll
        for (int j = 0; j < 4; j++) acc[i][j] = 0ull;

    const float* xb = x + (size_t)b * CIN * HWSZ;

    for (int ic0 = 0; ic0 < CIN; ic0 += 8) {
        // input tile (with halo) for 8 input channels
        for (int i = tid; i < 8 * 10 * 34; i += 256) {
            int ic = i / 340, rem = i % 340;
            int r = rem / 34, c = rem % 34;
            int gy = tile_y + r - 1, gx = tile_x + c - 1;
            float v = 0.f;
            if (gy >= 0 && gy < HW && gx >= 0 && gx < HW)
                v = xb[(ic0 + ic) * HWSZ + gy * HW + gx];
            in_s[i] = v;
        }
        // weight tile: sw[ic][k][oc_l] (coalesced; pad past OC with zeros)
        for (int i = tid; i < 8 * 9 * 64; i += 256) {
            int ic = i / 576, rem = i % 576;
            int k = rem / 64, ocl = rem % 64;
            int oc = ocb * 64 + ocl;
            sw[i] = (oc < OC) ? wt[((ic0 + ic) * 9 + k) * OC + oc] : 0.f;
        }
        __syncthreads();

#pragma unroll
        for (int ic = 0; ic < 8; ic++) {
            const float* ipb = &in_s[ic * 340 + ty * 34 + txq * 8];
#pragma unroll
            for (int dr = 0; dr < 3; dr++) {
                // pack the 10 input columns this thread needs, once
                unsigned long long v2[10];
                const float* ip = ipb + dr * 34;
#pragma unroll
                for (int c = 0; c < 10; c++) {
                    float f = ip[c];
                    v2[c] = pack2(f, f);
                }
#pragma unroll
                for (int dc = 0; dc < 3; dc++) {
                    const int k = dr * 3 + dc;
                    unsigned long long w2[4];
                    const float* wp = &sw[ic * 576 + k * 64 + oc_grp * 8];
#pragma unroll
                    for (int p = 0; p < 4; p++)
                        w2[p] = *reinterpret_cast<const unsigned long long*>(wp + 2 * p);
#pragma unroll
                    for (int px = 0; px < 8; px++)
#pragma unroll
                        for (int p = 0; p < 4; p++)
                            acc[px][p] = ffma2(v2[px + dc], w2[p], acc[px][p]);
                }
            }
        }
        __syncthreads();
    }

    // epilogue: two float4 stores per oc (coalesced)
    const int gy = tile_y + ty, gx0 = tile_x + txq * 8;
#pragma unroll
    for (int p = 0; p < 4; p++) {
        int oc = ocb * 64 + oc_grp * 8 + 2 * p;
        float lo[8], hi[8];
#pragma unroll
        for (int px = 0; px < 8; px++) unpack2(acc[px][p], lo[px], hi[px]);
        if (oc < OC) {
            float bz = bias[oc];
            float* yp = &y[((size_t)(b * OC + oc)) * HWSZ + gy * HW + gx0];
            *reinterpret_cast<float4*>(yp)     = make_float4(lo[0]+bz, lo[1]+bz, lo[2]+bz, lo[3]+bz);
            *reinterpret_cast<float4*>(yp + 4) = make_float4(lo[4]+bz, lo[5]+bz, lo[6]+bz, lo[7]+bz);
        }
        if (oc + 1 < OC) {
            float bz = bias[oc + 1];
            float* yp = &y[((size_t)(b * OC + oc + 1)) * HWSZ + gy * HW + gx0];
            *reinterpret_cast<float4*>(yp)     = make_float4(hi[0]+bz, hi[1]+bz, hi[2]+bz, hi[3]+bz);
            *reinterpret_cast<float4*>(yp + 4) = make_float4(hi[4]+bz, hi[5]+bz, hi[6]+bz, hi[7]+bz);
        }
    }
}

// ---------------- modulated deformable conv ----------------
// Block: 256 threads = 16 oc-groups (8 oc) x 16 px-threads (8 px: two float4
// groups). Spatial tile 32x4 = 128 px. Per (g,k): phase A computes bilinear
// params with ALL 256 threads (2 corners each); phase B gathers col[32][128];
// phase C is a 128oc x 128px x 32ic f32x2 GEMM slice.
__global__ __launch_bounds__(256, 2) void dcn_kernel(const float* __restrict__ x,
                                                     const float* __restrict__ bias,
                                                     float* __restrict__ y) {
    const int tid    = threadIdx.x;
    const int b      = blockIdx.y;
    const int tile_x = (blockIdx.x % 3) * 32;
    const int tile_y = (blockIdx.x / 3) * 4;
    const int oc_grp = tid >> 4;                 // 0..15 -> 8 oc each
    const int px_t   = tid & 15;                 // 0..15 -> 8 px each

    __shared__ __align__(8)  float s_w[32 * 128];    // [ic][oc]
    __shared__ __align__(16) float s_col[32 * 128];  // [ic][px]
    __shared__ int   s_idx[128][4];
    __shared__ float s_wgt[128][4];

    unsigned long long acc[8][4];
#pragma unroll
    for (int i = 0; i < 8; i++)
#pragma unroll
        for (int j = 0; j < 4; j++) acc[i][j] = 0ull;

    const float* cob = g_co + (size_t)b * OC2 * HWSZ;
    const float* xb  = x    + (size_t)b * CIN * HWSZ;

    for (int g = 0; g < NDG; g++) {
        for (int k = 0; k < 9; k++) {
            // Phase A: bilinear params, 2 corners per thread (all 256 active)
            {
                int px   = tid >> 1;
                int half = tid & 1;
                int gy   = tile_y + (px >> 5);
                int gx   = tile_x + (px & 31);
                int c_y  = g * 18 + 2 * k;
                const float* basep = cob + gy * HW + gx;
                float offy = basep[(size_t)c_y * HWSZ];
                float offx = basep[(size_t)(c_y + 1) * HWSZ];
                float mraw = basep[(size_t)(72 + g * 9 + k) * HWSZ];
                float m  = 1.f / (1.f + __expf(-mraw));
                float ys = (float)gy + (float)(k / 3 - 1) + offy;
                float xs = (float)gx + (float)(k % 3 - 1) + offx;
                float y0f = floorf(ys), x0f = floorf(xs);
                float fy = ys - y0f, fx = xs - x0f;
                int y0 = (int)y0f, x0 = (int)x0f;
#pragma unroll
                for (int c = 0; c < 2; c++) {
                    int cnr = 2 * half + c;
                    int dy = cnr >> 1, dx = cnr & 1;
                    int yi = y0 + dy, xi = x0 + dx;
                    bool valid = (yi >= 0) && (yi < HW) && (xi >= 0) && (xi < HW);
                    float wy = dy ? fy : (1.f - fy);
                    float wx = dx ? fx : (1.f - fx);
                    int yc = min(max(yi, 0), HW - 1);
                    int xc = min(max(xi, 0), HW - 1);
                    s_idx[px][cnr] = yc * HW + xc;
                    s_wgt[px][cnr] = valid ? (wy * wx * m) : 0.f;
                }
            }
            // Phase A2: weight tile [ic(32)][oc(128)] for this (g,k), coalesced
            {
                const float* wsrc = g_wdt + ((size_t)(g * 32) * 9 + k) * 128;
#pragma unroll
                for (int j = 0; j < 16; j++) {
                    int i  = tid + j * 256;
                    int ic = i >> 7, oc = i & 127;
                    s_w[i] = wsrc[ic * 9 * 128 + oc];
                }
            }
            __syncthreads();

            // Phase B: gather col tile (x is L2-resident; high MLP)
#pragma unroll
            for (int j = 0; j < 16; j++) {
                int e  = tid + j * 256;
                int ic = e >> 7, px = e & 127;
                const float* xp = xb + (size_t)(g * 32 + ic) * HWSZ;
                float v = s_wgt[px][0] * __ldg(xp + s_idx[px][0])
                        + s_wgt[px][1] * __ldg(xp + s_idx[px][1])
                        + s_wgt[px][2] * __ldg(xp + s_idx[px][2])
                        + s_wgt[px][3] * __ldg(xp + s_idx[px][3]);
                s_col[e] = v;
            }
            __syncthreads();

            // Phase C: 128oc x 128px x 32ic GEMM slice
#pragma unroll 8
            for (int ic = 0; ic < 32; ic++) {
                float4 ca = *reinterpret_cast<const float4*>(&s_col[ic * 128 + px_t * 4]);
                float4 cb = *reinterpret_cast<const float4*>(&s_col[ic * 128 + 64 + px_t * 4]);
                unsigned long long w2[4];
                const float* wp = &s_w[ic * 128 + oc_grp * 8];
#pragma unroll
                for (int p = 0; p < 4; p++)
                    w2[p] = *reinterpret_cast<const unsigned long long*>(wp + 2 * p);
                float cv[8] = {ca.x, ca.y, ca.z, ca.w, cb.x, cb.y, cb.z, cb.w};
#pragma unroll
                for (int px = 0; px < 8; px++) {
                    unsigned long long v2 = pack2(cv[px], cv[px]);
#pragma unroll
                    for (int p = 0; p < 4; p++)
                        acc[px][p] = ffma2(v2, w2[p], acc[px][p]);
                }
            }
            __syncthreads();
        }
    }

    // epilogue: group a = px_t*4 (rows 0-1), group b = 64 + px_t*4 (rows 2-3)
    const int gya = tile_y + (px_t >> 3);
    const int gyb = gya + 2;
    const int gx0 = tile_x + ((px_t * 4) & 31);
#pragma unroll
    for (int p = 0; p < 4; p++) {
        int oc = oc_grp * 8 + 2 * p;
        float lo[8], hi[8];
#pragma unroll
        for (int px = 0; px < 8; px++) unpack2(acc[px][p], lo[px], hi[px]);
        {
            float bz = bias[oc];
            float* yp = &y[((size_t)(b * OC1 + oc)) * HWSZ];
            *reinterpret_cast<float4*>(yp + gya * HW + gx0) = make_float4(lo[0]+bz, lo[1]+bz, lo[2]+bz, lo[3]+bz);
            *reinterpret_cast<float4*>(yp + gyb * HW + gx0) = make_float4(lo[4]+bz, lo[5]+bz, lo[6]+bz, lo[7]+bz);
        }
        {
            float bz = bias[oc + 1];
            float* yp = &y[((size_t)(b * OC1 + oc + 1)) * HWSZ];
            *reinterpret_cast<float4*>(yp + gya * HW + gx0) = make_float4(hi[0]+bz, hi[1]+bz, hi[2]+bz, hi[3]+bz);
            *reinterpret_cast<float4*>(yp + gyb * HW + gx0) = make_float4(hi[4]+bz, hi[5]+bz, hi[6]+bz, hi[7]+bz);
        }
    }
}

// ---------------- launch ----------------
extern "C" void kernel_launch(void* const* d_in, const int* in_sizes, int n_in,
                              void* d_out, int out_size) {
    (void)in_sizes; (void)n_in; (void)out_size;
    const float* x_vq  = (const float*)d_in[0];
    const float* w_off = (const float*)d_in[1];
    const float* b_off = (const float*)d_in[2];
    const float* w_co  = (const float*)d_in[3];
    const float* b_co  = (const float*)d_in[4];
    const float* w_dcn = (const float*)d_in[5];
    const float* b_dcn = (const float*)d_in[6];
    float* out = (float*)d_out;

    transpose_w_kernel<<<(OC1 * CIN * 9 + 255) / 256, 256>>>(w_off, OC1, 0);
    transpose_w_kernel<<<(OC2 * CIN * 9 + 255) / 256, 256>>>(w_co,  OC2, 1);
    transpose_w_kernel<<<(OC1 * CIN * 9 + 255) / 256, 256>>>(w_dcn, OC1, 2);

    dim3 cgrid(36, BATCH, 2);   // 3x12 spatial tiles, batch, 2 oc-blocks of 64
    conv3x3_kernel<OC1, 0><<<cgrid, 256>>>(x_vq, b_off);
    conv3x3_kernel<OC2, 1><<<cgrid, 256>>>(nullptr, b_co);

    dim3 dgrid(3 * 24, BATCH);  // 32x4 px tiles
    dcn_kernel<<<dgrid, 256>>>(x_vq, b_dcn, out);
}

// round 5
// speedup vs baseline: 1.7091x; 1.7091x over previous
#include <cuda_runtime.h>
#include <cstdint>

#define CIN   128
#define HW    96
#define HWSZ  9216
#define BATCH 4
#define OC1   128
#define OC2   108
#define NDG   4

// ---------------- scratch (static device globals; no allocs) ----------------
__device__ float g_xres[BATCH * OC1 * HWSZ];     // conv1 output
__device__ float g_co  [BATCH * OC2 * HWSZ];     // conv2 output
__device__ float g_wA1 [9 * 4 * 128 * 32];       // conv1 W packed [k*4+icc][oc][icl], tf32
__device__ float g_wA2 [9 * 4 * 128 * 32];       // conv2 W packed (oc>=108 zero)
__device__ float g_wd2 [36 * 128 * 32];          // dcn W packed [g*9+k][oc][icl], tf32

// ---------------- helpers ----------------
// cvt.rna.tf32.f32 requires a .b32 destination register -> "=r" constraint.
__device__ __forceinline__ uint32_t tf32_bits(float x) {
    uint32_t r; asm("cvt.rna.tf32.f32 %0, %1;" : "=r"(r) : "f"(x)); return r;
}
__device__ __forceinline__ float to_tf32(float x) {
    return __uint_as_float(tf32_bits(x));
}
__device__ __forceinline__ void mma8(float c[4], const uint32_t a[4], const uint32_t b[2]) {
    asm volatile("mma.sync.aligned.m16n8k8.row.col.f32.tf32.tf32.f32 "
        "{%0,%1,%2,%3}, {%4,%5,%6,%7}, {%8,%9}, {%0,%1,%2,%3};"
        : "+f"(c[0]), "+f"(c[1]), "+f"(c[2]), "+f"(c[3])
        : "r"(a[0]), "r"(a[1]), "r"(a[2]), "r"(a[3]), "r"(b[0]), "r"(b[1]));
}
__device__ __forceinline__ uint32_t fbits(float x) { return __float_as_uint(x); }

// ---------------- weight prep ----------------
// conv: dst[(k*4+icc)*4096 + oc*32 + icl] = tf32(w[oc][icc*32+icl][k])
__global__ void prep_wA_kernel(const float* __restrict__ w, int OC, int which) {
    float* dst = which ? g_wA2 : g_wA1;
    int i = blockIdx.x * 256 + threadIdx.x;
    if (i >= 9 * 4 * 128 * 32) return;
    int icl = i & 31, oc = (i >> 5) & 127, icc = (i >> 12) & 3, k = i >> 14;
    int ic = icc * 32 + icl;
    float v = (oc < OC) ? w[(oc * CIN + ic) * 9 + k] : 0.f;
    dst[i] = to_tf32(v);
}
// dcn: dst[(g*9+k)*4096 + oc*32 + icl] = tf32(w[oc][g*32+icl][k])
__global__ void prep_wd_kernel(const float* __restrict__ w) {
    int i = blockIdx.x * 256 + threadIdx.x;
    if (i >= 36 * 128 * 32) return;
    int icl = i & 31, oc = (i >> 5) & 127, chunk = i >> 12;
    int g = chunk / 9, k = chunk % 9;
    g_wd2[i] = to_tf32(w[(oc * CIN + g * 32 + icl) * 9 + k]);
}

// ---------------- tf32 mma conv3x3 ----------------
// CTA: 256 thr = 8 warps (2 M x 4 N). Tile M=128 oc, N=128 px (32x4 spatial).
// Warp tile 64x32 -> 4 mtiles x 4 ntiles of m16n8k8, K=1152 as 144 k8-steps.
// smem: stg[32 ic][232] input tile (tf32), s_w[2][128][36] weight chunks (double buf).
#define STG_S 232
#define SW_S  36
#define CONV_SMEM ((32*STG_S + 2*128*SW_S) * 4)   // 29696 + 36864 = 66560 B

template<int OC, int MODE>
__global__ void __launch_bounds__(256) conv_mma_kernel(const float* __restrict__ xin,
                                                       const float* __restrict__ bias) {
    extern __shared__ float sm[];
    float* stg = sm;                         // 32*232
    float* swb0 = sm + 32 * STG_S;           // 128*36
    float* swb1 = swb0 + 128 * SW_S;

    const float* x  = (MODE == 0) ? xin : g_xres;
    const float* wA = (MODE == 0) ? g_wA1 : g_wA2;
    float*       y  = (MODE == 0) ? g_xres : g_co;

    const int tid = threadIdx.x;
    const int wid = tid >> 5, lane = tid & 31;
    const int warp_m = wid >> 2, warp_n = wid & 3;
    const int lm = lane >> 2, lk = lane & 3;
    const int b = blockIdx.y;
    const int tile_x = (blockIdx.x % 3) * 32;
    const int tile_y = (blockIdx.x / 3) * 4;

    float c[4][4][4];
#pragma unroll
    for (int mt = 0; mt < 4; mt++)
#pragma unroll
        for (int nt = 0; nt < 4; nt++)
#pragma unroll
            for (int i = 0; i < 4; i++) c[mt][nt][i] = 0.f;

    int pxbase[4], arow[4];
#pragma unroll
    for (int nt = 0; nt < 4; nt++) {
        int px = warp_n * 32 + nt * 8 + lm;
        pxbase[nt] = (px >> 5) * 34 + (px & 31);
    }
#pragma unroll
    for (int mt = 0; mt < 4; mt++)
        arow[mt] = (warp_m * 64 + mt * 16 + lm) * SW_S;

    const float* xb = x + (size_t)b * CIN * HWSZ;

    for (int icc = 0; icc < 4; icc++) {
        __syncthreads();   // prior compute done reading stg/s_w
        // stage input chunk: 32 ic x 6 rows x 34 cols, tf32
        for (int i = tid; i < 32 * 204; i += 256) {
            int ic = i / 204, rem = i % 204;
            int r = rem / 34, cc = rem % 34;
            int gy = tile_y + r - 1, gx = tile_x + cc - 1;
            float v = 0.f;
            if (gy >= 0 && gy < HW && gx >= 0 && gx < HW)
                v = xb[(size_t)(icc * 32 + ic) * HWSZ + gy * HW + gx];
            stg[ic * STG_S + r * 34 + cc] = to_tf32(v);
        }
        // preload weight chunk (icc, k=0)
        {
            const float* Asrc = wA + (size_t)(0 * 4 + icc) * 4096;
#pragma unroll
            for (int j = 0; j < 16; j++) {
                int i = tid + j * 256;
                swb0[(i >> 5) * SW_S + (i & 31)] = Asrc[i];
            }
        }
        __syncthreads();

        for (int k = 0; k < 9; k++) {
            float* swc = (k & 1) ? swb1 : swb0;
            float* swn = (k & 1) ? swb0 : swb1;
            if (k < 8) {   // prefetch next chunk
                const float* Asrc = wA + (size_t)((k + 1) * 4 + icc) * 4096;
#pragma unroll
                for (int j = 0; j < 16; j++) {
                    int i = tid + j * 256;
                    swn[(i >> 5) * SW_S + (i & 31)] = Asrc[i];
                }
            }
            const int koff = (k / 3) * 34 + (k % 3);
#pragma unroll
            for (int s = 0; s < 4; s++) {
                const int icl0 = s * 8;
                uint32_t A[4][4], B[4][2];
#pragma unroll
                for (int mt = 0; mt < 4; mt++) {
                    const float* ap = swc + arow[mt] + icl0 + lk;
                    A[mt][0] = fbits(ap[0]);
                    A[mt][1] = fbits(ap[8 * SW_S]);
                    A[mt][2] = fbits(ap[4]);
                    A[mt][3] = fbits(ap[8 * SW_S + 4]);
                }
#pragma unroll
                for (int nt = 0; nt < 4; nt++) {
                    const float* bp = stg + (icl0 + lk) * STG_S + pxbase[nt] + koff;
                    B[nt][0] = fbits(bp[0]);
                    B[nt][1] = fbits(bp[4 * STG_S]);
                }
#pragma unroll
                for (int mt = 0; mt < 4; mt++)
#pragma unroll
                    for (int nt = 0; nt < 4; nt++)
                        mma8(c[mt][nt], A[mt], B[nt]);
            }
            __syncthreads();
        }
    }

    // epilogue
#pragma unroll
    for (int mt = 0; mt < 4; mt++) {
        int oc0 = warp_m * 64 + mt * 16 + lm;
        int oc1 = oc0 + 8;
#pragma unroll
        for (int nt = 0; nt < 4; nt++) {
            int px0 = warp_n * 32 + nt * 8 + lk * 2;
            int gy = tile_y + (px0 >> 5), gx = tile_x + (px0 & 31);
            if (oc0 < OC) {
                float bz = bias[oc0];
                float2 o = make_float2(c[mt][nt][0] + bz, c[mt][nt][1] + bz);
                *reinterpret_cast<float2*>(&y[((size_t)(b * OC + oc0)) * HWSZ + gy * HW + gx]) = o;
            }
            if (oc1 < OC) {
                float bz = bias[oc1];
                float2 o = make_float2(c[mt][nt][2] + bz, c[mt][nt][3] + bz);
                *reinterpret_cast<float2*>(&y[((size_t)(b * OC + oc1)) * HWSZ + gy * HW + gx]) = o;
            }
        }
    }
}

// ---------------- modulated deformable conv (gather + tf32 mma GEMM) ----------------
// CTA: 256 thr = 8 warps (4 M x 2 N). Tile M=128 oc, N=64 px (32x2).
// Per (g,k): phase A bilinear params (1 corner/thread), phase B gather col[32][72],
// phase C mma: warp tile 32x32 -> 2 mtiles x 4 ntiles, 4 k8-steps.
#define COL_S 72
__global__ void __launch_bounds__(256) dcn_mma_kernel(const float* __restrict__ x,
                                                      const float* __restrict__ bias,
                                                      float* __restrict__ y) {
    __shared__ float s_w[2][128 * SW_S];    // 36864 B
    __shared__ float s_col[32 * COL_S];     // 9216 B
    __shared__ int   s_idx[64][4];
    __shared__ float s_wgt[64][4];

    const int tid = threadIdx.x;
    const int wid = tid >> 5, lane = tid & 31;
    const int warp_m = wid >> 1, warp_n = wid & 1;
    const int lm = lane >> 2, lk = lane & 3;
    const int b = blockIdx.y;
    const int tile_x = (blockIdx.x % 3) * 32;
    const int tile_y = (blockIdx.x / 3) * 2;

    float c[2][4][4];
#pragma unroll
    for (int mt = 0; mt < 2; mt++)
#pragma unroll
        for (int nt = 0; nt < 4; nt++)
#pragma unroll
            for (int i = 0; i < 4; i++) c[mt][nt][i] = 0.f;

    const float* cob = g_co + (size_t)b * OC2 * HWSZ;
    const float* xb  = x    + (size_t)b * CIN * HWSZ;

    // preload chunk 0
#pragma unroll
    for (int j = 0; j < 16; j++) {
        int i = tid + j * 256;
        s_w[0][(i >> 5) * SW_S + (i & 31)] = g_wd2[i];
    }

    int it = 0;
    for (int g = 0; g < NDG; g++) {
        for (int k = 0; k < 9; k++, it++) {
            const int buf = it & 1;
            // phase A: 1 corner per thread (px = tid>>2, cnr = tid&3)
            {
                int px = tid >> 2, cnr = tid & 3;
                int gy = tile_y + (px >> 5), gx = tile_x + (px & 31);
                int c_y = g * 18 + 2 * k;
                const float* basep = cob + gy * HW + gx;
                float offy = basep[(size_t)c_y * HWSZ];
                float offx = basep[(size_t)(c_y + 1) * HWSZ];
                float mraw = basep[(size_t)(72 + g * 9 + k) * HWSZ];
                float m  = 1.f / (1.f + __expf(-mraw));
                float ys = (float)gy + (float)(k / 3 - 1) + offy;
                float xs = (float)gx + (float)(k % 3 - 1) + offx;
                float y0f = floorf(ys), x0f = floorf(xs);
                float fy = ys - y0f, fx = xs - x0f;
                int y0 = (int)y0f, x0 = (int)x0f;
                int dy = cnr >> 1, dx = cnr & 1;
                int yi = y0 + dy, xi = x0 + dx;
                bool valid = (yi >= 0) && (yi < HW) && (xi >= 0) && (xi < HW);
                float wy = dy ? fy : (1.f - fy);
                float wx = dx ? fx : (1.f - fx);
                int yc = min(max(yi, 0), HW - 1);
                int xc = min(max(xi, 0), HW - 1);
                s_idx[px][cnr] = yc * HW + xc;
                s_wgt[px][cnr] = valid ? (wy * wx * m) : 0.f;
            }
            // prefetch next weight chunk
            if (it < 35) {
                const float* Wn = g_wd2 + (size_t)(it + 1) * 4096;
                float* swn = s_w[buf ^ 1];
#pragma unroll
                for (int j = 0; j < 16; j++) {
                    int i = tid + j * 256;
                    swn[(i >> 5) * SW_S + (i & 31)] = Wn[i];
                }
            }
            __syncthreads();

            // phase B: gather col[ic][px] (tf32)
#pragma unroll
            for (int j = 0; j < 8; j++) {
                int e = tid + j * 256;
                int ic = e >> 6, px = e & 63;
                const float* xp = xb + (size_t)(g * 32 + ic) * HWSZ;
                float v = s_wgt[px][0] * __ldg(xp + s_idx[px][0])
                        + s_wgt[px][1] * __ldg(xp + s_idx[px][1])
                        + s_wgt[px][2] * __ldg(xp + s_idx[px][2])
                        + s_wgt[px][3] * __ldg(xp + s_idx[px][3]);
                s_col[ic * COL_S + px] = to_tf32(v);
            }
            __syncthreads();

            // phase C: mma
            const float* swc = s_w[buf];
#pragma unroll
            for (int s = 0; s < 4; s++) {
                const int icl0 = s * 8;
                uint32_t A[2][4], B[4][2];
#pragma unroll
                for (int mt = 0; mt < 2; mt++) {
                    const float* ap = swc + (warp_m * 32 + mt * 16 + lm) * SW_S + icl0 + lk;
                    A[mt][0] = fbits(ap[0]);
                    A[mt][1] = fbits(ap[8 * SW_S]);
                    A[mt][2] = fbits(ap[4]);
                    A[mt][3] = fbits(ap[8 * SW_S + 4]);
                }
#pragma unroll
                for (int nt = 0; nt < 4; nt++) {
                    const float* bp = s_col + (icl0 + lk) * COL_S + warp_n * 32 + nt * 8 + lm;
                    B[nt][0] = fbits(bp[0]);
                    B[nt][1] = fbits(bp[4 * COL_S]);
                }
#pragma unroll
                for (int mt = 0; mt < 2; mt++)
#pragma unroll
                    for (int nt = 0; nt < 4; nt++)
                        mma8(c[mt][nt], A[mt], B[nt]);
            }
            __syncthreads();
        }
    }

    // epilogue
#pragma unroll
    for (int mt = 0; mt < 2; mt++) {
        int oc0 = warp_m * 32 + mt * 16 + lm;
        int oc1 = oc0 + 8;
        float bz0 = bias[oc0], bz1 = bias[oc1];
#pragma unroll
        for (int nt = 0; nt < 4; nt++) {
            int px0 = warp_n * 32 + nt * 8 + lk * 2;
            int gy = tile_y + (px0 >> 5), gx = tile_x + (px0 & 31);
            *reinterpret_cast<float2*>(&y[((size_t)(b * OC1 + oc0)) * HWSZ + gy * HW + gx]) =
                make_float2(c[mt][nt][0] + bz0, c[mt][nt][1] + bz0);
            *reinterpret_cast<float2*>(&y[((size_t)(b * OC1 + oc1)) * HWSZ + gy * HW + gx]) =
                make_float2(c[mt][nt][2] + bz1, c[mt][nt][3] + bz1);
        }
    }
}

// ---------------- launch ----------------
extern "C" void kernel_launch(void* const* d_in, const int* in_sizes, int n_in,
                              void* d_out, int out_size) {
    (void)in_sizes; (void)n_in; (void)out_size;
    const float* x_vq  = (const float*)d_in[0];
    const float* w_off = (const float*)d_in[1];
    const float* b_off = (const float*)d_in[2];
    const float* w_co  = (const float*)d_in[3];
    const float* b_co  = (const float*)d_in[4];
    const float* w_dcn = (const float*)d_in[5];
    const float* b_dcn = (const float*)d_in[6];
    float* out = (float*)d_out;

    cudaFuncSetAttribute(conv_mma_kernel<OC1, 0>, cudaFuncAttributeMaxDynamicSharedMemorySize, CONV_SMEM);
    cudaFuncSetAttribute(conv_mma_kernel<OC2, 1>, cudaFuncAttributeMaxDynamicSharedMemorySize, CONV_SMEM);

    prep_wA_kernel<<<(9 * 4 * 128 * 32 + 255) / 256, 256>>>(w_off, OC1, 0);
    prep_wA_kernel<<<(9 * 4 * 128 * 32 + 255) / 256, 256>>>(w_co,  OC2, 1);
    prep_wd_kernel<<<(36 * 128 * 32 + 255) / 256, 256>>>(w_dcn);

    dim3 cgrid(72, BATCH);   // 3x24 tiles of 32x4 px, 128 oc per CTA
    conv_mma_kernel<OC1, 0><<<cgrid, 256, CONV_SMEM>>>(x_vq, b_off);
    conv_mma_kernel<OC2, 1><<<cgrid, 256, CONV_SMEM>>>(nullptr, b_co);

    dim3 dgrid(3 * 48, BATCH);  // 32x2 px tiles
    dcn_mma_kernel<<<dgrid, 256>>>(x_vq, b_dcn, out);
}

// round 6
// speedup vs baseline: 1.8926x; 1.1074x over previous
#include <cuda_runtime.h>
#include <cstdint>

#define CIN   128
#define HW    96
#define HWSZ  9216
#define BATCH 4
#define OC1   128
#define OC2   108
#define NDG   4

// ---------------- scratch (static device globals; no allocs) ----------------
__device__ float g_xres[BATCH * OC1 * HWSZ];     // conv1 output
__device__ float g_co  [BATCH * OC2 * HWSZ];     // conv2 output
__device__ float g_wA1 [9 * 4 * 128 * 32];       // conv1 W packed [k*4+icc][oc][icl], tf32
__device__ float g_wA2 [9 * 4 * 128 * 32];       // conv2 W packed (oc>=108 zero)
__device__ float g_wd2 [36 * 128 * 32];          // dcn W packed [g*9+k][oc][icl], tf32

// ---------------- helpers ----------------
// cvt.rna.tf32.f32 requires a .b32 destination register -> "=r" constraint.
__device__ __forceinline__ uint32_t tf32_bits(float x) {
    uint32_t r; asm("cvt.rna.tf32.f32 %0, %1;" : "=r"(r) : "f"(x)); return r;
}
__device__ __forceinline__ float to_tf32(float x) {
    return __uint_as_float(tf32_bits(x));
}
__device__ __forceinline__ void mma8(float c[4], const uint32_t a[4], const uint32_t b[2]) {
    asm volatile("mma.sync.aligned.m16n8k8.row.col.f32.tf32.tf32.f32 "
        "{%0,%1,%2,%3}, {%4,%5,%6,%7}, {%8,%9}, {%0,%1,%2,%3};"
        : "+f"(c[0]), "+f"(c[1]), "+f"(c[2]), "+f"(c[3])
        : "r"(a[0]), "r"(a[1]), "r"(a[2]), "r"(a[3]), "r"(b[0]), "r"(b[1]));
}
__device__ __forceinline__ uint32_t fbits(float x) { return __float_as_uint(x); }

// ---------------- weight prep ----------------
// conv: dst[(k*4+icc)*4096 + oc*32 + icl] = tf32(w[oc][icc*32+icl][k])
__global__ void prep_wA_kernel(const float* __restrict__ w, int OC, int which) {
    float* dst = which ? g_wA2 : g_wA1;
    int i = blockIdx.x * 256 + threadIdx.x;
    if (i >= 9 * 4 * 128 * 32) return;
    int icl = i & 31, oc = (i >> 5) & 127, icc = (i >> 12) & 3, k = i >> 14;
    int ic = icc * 32 + icl;
    float v = (oc < OC) ? w[(oc * CIN + ic) * 9 + k] : 0.f;
    dst[i] = to_tf32(v);
}
// dcn: dst[(g*9+k)*4096 + oc*32 + icl] = tf32(w[oc][g*32+icl][k])
__global__ void prep_wd_kernel(const float* __restrict__ w) {
    int i = blockIdx.x * 256 + threadIdx.x;
    if (i >= 36 * 128 * 32) return;
    int icl = i & 31, oc = (i >> 5) & 127, chunk = i >> 12;
    int g = chunk / 9, k = chunk % 9;
    g_wd2[i] = to_tf32(w[(oc * CIN + g * 32 + icl) * 9 + k]);
}

// ---------------- tf32 mma conv3x3 ----------------
// CTA: 256 thr = 8 warps (2 M x 4 N). Tile M=128 oc, N=128 px (32x4 spatial).
// Warp tile 64x32 -> 4 mtiles x 4 ntiles of m16n8k8, K=1152 as 144 k8-steps.
// __launch_bounds__(256,2): cap 128 regs -> 2 CTAs/SM -> 1-wave grid, barriers overlap.
#define STG_S 232
#define SW_S  36
#define CONV_SMEM ((32*STG_S + 2*128*SW_S) * 4)   // 29696 + 36864 = 66560 B

template<int OC, int MODE>
__global__ void __launch_bounds__(256, 2) conv_mma_kernel(const float* __restrict__ xin,
                                                          const float* __restrict__ bias) {
    extern __shared__ float sm[];
    float* stg = sm;                         // 32*232
    float* swb0 = sm + 32 * STG_S;           // 128*36
    float* swb1 = swb0 + 128 * SW_S;

    const float* x  = (MODE == 0) ? xin : g_xres;
    const float* wA = (MODE == 0) ? g_wA1 : g_wA2;
    float*       y  = (MODE == 0) ? g_xres : g_co;

    const int tid = threadIdx.x;
    const int wid = tid >> 5, lane = tid & 31;
    const int warp_m = wid >> 2, warp_n = wid & 3;
    const int lm = lane >> 2, lk = lane & 3;
    const int b = blockIdx.y;
    const int tile_x = (blockIdx.x % 3) * 32;
    const int tile_y = (blockIdx.x / 3) * 4;

    float c[4][4][4];
#pragma unroll
    for (int mt = 0; mt < 4; mt++)
#pragma unroll
        for (int nt = 0; nt < 4; nt++)
#pragma unroll
            for (int i = 0; i < 4; i++) c[mt][nt][i] = 0.f;

    int pxbase[4], arow[4];
#pragma unroll
    for (int nt = 0; nt < 4; nt++) {
        int px = warp_n * 32 + nt * 8 + lm;
        pxbase[nt] = (px >> 5) * 34 + (px & 31);
    }
#pragma unroll
    for (int mt = 0; mt < 4; mt++)
        arow[mt] = (warp_m * 64 + mt * 16 + lm) * SW_S;

    const float* xb = x + (size_t)b * CIN * HWSZ;

    for (int icc = 0; icc < 4; icc++) {
        __syncthreads();   // prior compute done reading stg/s_w
        // stage input chunk: 32 ic x 6 rows x 34 cols, tf32
        for (int i = tid; i < 32 * 204; i += 256) {
            int ic = i / 204, rem = i % 204;
            int r = rem / 34, cc = rem % 34;
            int gy = tile_y + r - 1, gx = tile_x + cc - 1;
            float v = 0.f;
            if (gy >= 0 && gy < HW && gx >= 0 && gx < HW)
                v = xb[(size_t)(icc * 32 + ic) * HWSZ + gy * HW + gx];
            stg[ic * STG_S + r * 34 + cc] = to_tf32(v);
        }
        // preload weight chunk (icc, k=0)
        {
            const float* Asrc = wA + (size_t)(0 * 4 + icc) * 4096;
#pragma unroll
            for (int j = 0; j < 16; j++) {
                int i = tid + j * 256;
                swb0[(i >> 5) * SW_S + (i & 31)] = Asrc[i];
            }
        }
        __syncthreads();

        for (int k = 0; k < 9; k++) {
            float* swc = (k & 1) ? swb1 : swb0;
            float* swn = (k & 1) ? swb0 : swb1;
            if (k < 8) {   // prefetch next chunk
                const float* Asrc = wA + (size_t)((k + 1) * 4 + icc) * 4096;
#pragma unroll
                for (int j = 0; j < 16; j++) {
                    int i = tid + j * 256;
                    swn[(i >> 5) * SW_S + (i & 31)] = Asrc[i];
                }
            }
            const int koff = (k / 3) * 34 + (k % 3);
#pragma unroll
            for (int s = 0; s < 4; s++) {
                const int icl0 = s * 8;
                uint32_t A[4][4], B[4][2];
#pragma unroll
                for (int mt = 0; mt < 4; mt++) {
                    const float* ap = swc + arow[mt] + icl0 + lk;
                    A[mt][0] = fbits(ap[0]);
                    A[mt][1] = fbits(ap[8 * SW_S]);
                    A[mt][2] = fbits(ap[4]);
                    A[mt][3] = fbits(ap[8 * SW_S + 4]);
                }
#pragma unroll
                for (int nt = 0; nt < 4; nt++) {
                    const float* bp = stg + (icl0 + lk) * STG_S + pxbase[nt] + koff;
                    B[nt][0] = fbits(bp[0]);
                    B[nt][1] = fbits(bp[4 * STG_S]);
                }
#pragma unroll
                for (int mt = 0; mt < 4; mt++)
#pragma unroll
                    for (int nt = 0; nt < 4; nt++)
                        mma8(c[mt][nt], A[mt], B[nt]);
            }
            __syncthreads();
        }
    }

    // epilogue
#pragma unroll
    for (int mt = 0; mt < 4; mt++) {
        int oc0 = warp_m * 64 + mt * 16 + lm;
        int oc1 = oc0 + 8;
#pragma unroll
        for (int nt = 0; nt < 4; nt++) {
            int px0 = warp_n * 32 + nt * 8 + lk * 2;
            int gy = tile_y + (px0 >> 5), gx = tile_x + (px0 & 31);
            if (oc0 < OC) {
                float bz = bias[oc0];
                float2 o = make_float2(c[mt][nt][0] + bz, c[mt][nt][1] + bz);
                *reinterpret_cast<float2*>(&y[((size_t)(b * OC + oc0)) * HWSZ + gy * HW + gx]) = o;
            }
            if (oc1 < OC) {
                float bz = bias[oc1];
                float2 o = make_float2(c[mt][nt][2] + bz, c[mt][nt][3] + bz);
                *reinterpret_cast<float2*>(&y[((size_t)(b * OC + oc1)) * HWSZ + gy * HW + gx]) = o;
            }
        }
    }
}

// ---------------- modulated deformable conv (gather + tf32 mma GEMM) ----------------
// CTA: 256 thr = 8 warps (4 M x 2 N). Tile M=128 oc, N=64 px (32x2).
// __launch_bounds__(256,2): guarantee >=2 CTAs/SM to hide gather latency.
#define COL_S 72
__global__ void __launch_bounds__(256, 2) dcn_mma_kernel(const float* __restrict__ x,
                                                         const float* __restrict__ bias,
                                                         float* __restrict__ y) {
    __shared__ float s_w[2][128 * SW_S];    // 36864 B
    __shared__ float s_col[32 * COL_S];     // 9216 B
    __shared__ int   s_idx[64][4];
    __shared__ float s_wgt[64][4];

    const int tid = threadIdx.x;
    const int wid = tid >> 5, lane = tid & 31;
    const int warp_m = wid >> 1, warp_n = wid & 1;
    const int lm = lane >> 2, lk = lane & 3;
    const int b = blockIdx.y;
    const int tile_x = (blockIdx.x % 3) * 32;
    const int tile_y = (blockIdx.x / 3) * 2;

    float c[2][4][4];
#pragma unroll
    for (int mt = 0; mt < 2; mt++)
#pragma unroll
        for (int nt = 0; nt < 4; nt++)
#pragma unroll
            for (int i = 0; i < 4; i++) c[mt][nt][i] = 0.f;

    const float* cob = g_co + (size_t)b * OC2 * HWSZ;
    const float* xb  = x    + (size_t)b * CIN * HWSZ;

    // preload chunk 0
#pragma unroll
    for (int j = 0; j < 16; j++) {
        int i = tid + j * 256;
        s_w[0][(i >> 5) * SW_S + (i & 31)] = g_wd2[i];
    }

    int it = 0;
    for (int g = 0; g < NDG; g++) {
        for (int k = 0; k < 9; k++, it++) {
            const int buf = it & 1;
            // phase A: 1 corner per thread (px = tid>>2, cnr = tid&3)
            {
                int px = tid >> 2, cnr = tid & 3;
                int gy = tile_y + (px >> 5), gx = tile_x + (px & 31);
                int c_y = g * 18 + 2 * k;
                const float* basep = cob + gy * HW + gx;
                float offy = basep[(size_t)c_y * HWSZ];
                float offx = basep[(size_t)(c_y + 1) * HWSZ];
                float mraw = basep[(size_t)(72 + g * 9 + k) * HWSZ];
                float m  = 1.f / (1.f + __expf(-mraw));
                float ys = (float)gy + (float)(k / 3 - 1) + offy;
                float xs = (float)gx + (float)(k % 3 - 1) + offx;
                float y0f = floorf(ys), x0f = floorf(xs);
                float fy = ys - y0f, fx = xs - x0f;
                int y0 = (int)y0f, x0 = (int)x0f;
                int dy = cnr >> 1, dx = cnr & 1;
                int yi = y0 + dy, xi = x0 + dx;
                bool valid = (yi >= 0) && (yi < HW) && (xi >= 0) && (xi < HW);
                float wy = dy ? fy : (1.f - fy);
                float wx = dx ? fx : (1.f - fx);
                int yc = min(max(yi, 0), HW - 1);
                int xc = min(max(xi, 0), HW - 1);
                s_idx[px][cnr] = yc * HW + xc;
                s_wgt[px][cnr] = valid ? (wy * wx * m) : 0.f;
            }
            // prefetch next weight chunk
            if (it < 35) {
                const float* Wn = g_wd2 + (size_t)(it + 1) * 4096;
                float* swn = s_w[buf ^ 1];
#pragma unroll
                for (int j = 0; j < 16; j++) {
                    int i = tid + j * 256;
                    swn[(i >> 5) * SW_S + (i & 31)] = Wn[i];
                }
            }
            __syncthreads();

            // phase B: gather col[ic][px] (tf32)
#pragma unroll
            for (int j = 0; j < 8; j++) {
                int e = tid + j * 256;
                int ic = e >> 6, px = e & 63;
                const float* xp = xb + (size_t)(g * 32 + ic) * HWSZ;
                float v = s_wgt[px][0] * __ldg(xp + s_idx[px][0])
                        + s_wgt[px][1] * __ldg(xp + s_idx[px][1])
                        + s_wgt[px][2] * __ldg(xp + s_idx[px][2])
                        + s_wgt[px][3] * __ldg(xp + s_idx[px][3]);
                s_col[ic * COL_S + px] = to_tf32(v);
            }
            __syncthreads();

            // phase C: mma
            const float* swc = s_w[buf];
#pragma unroll
            for (int s = 0; s < 4; s++) {
                const int icl0 = s * 8;
                uint32_t A[2][4], B[4][2];
#pragma unroll
                for (int mt = 0; mt < 2; mt++) {
                    const float* ap = swc + (warp_m * 32 + mt * 16 + lm) * SW_S + icl0 + lk;
                    A[mt][0] = fbits(ap[0]);
                    A[mt][1] = fbits(ap[8 * SW_S]);
                    A[mt][2] = fbits(ap[4]);
                    A[mt][3] = fbits(ap[8 * SW_S + 4]);
                }
#pragma unroll
                for (int nt = 0; nt < 4; nt++) {
                    const float* bp = s_col + (icl0 + lk) * COL_S + warp_n * 32 + nt * 8 + lm;
                    B[nt][0] = fbits(bp[0]);
                    B[nt][1] = fbits(bp[4 * COL_S]);
                }
#pragma unroll
                for (int mt = 0; mt < 2; mt++)
#pragma unroll
                    for (int nt = 0; nt < 4; nt++)
                        mma8(c[mt][nt], A[mt], B[nt]);
            }
            __syncthreads();
        }
    }

    // epilogue
#pragma unroll
    for (int mt = 0; mt < 2; mt++) {
        int oc0 = warp_m * 32 + mt * 16 + lm;
        int oc1 = oc0 + 8;
        float bz0 = bias[oc0], bz1 = bias[oc1];
#pragma unroll
        for (int nt = 0; nt < 4; nt++) {
            int px0 = warp_n * 32 + nt * 8 + lk * 2;
            int gy = tile_y + (px0 >> 5), gx = tile_x + (px0 & 31);
            *reinterpret_cast<float2*>(&y[((size_t)(b * OC1 + oc0)) * HWSZ + gy * HW + gx]) =
                make_float2(c[mt][nt][0] + bz0, c[mt][nt][1] + bz0);
            *reinterpret_cast<float2*>(&y[((size_t)(b * OC1 + oc1)) * HWSZ + gy * HW + gx]) =
                make_float2(c[mt][nt][2] + bz1, c[mt][nt][3] + bz1);
        }
    }
}

// ---------------- launch ----------------
extern "C" void kernel_launch(void* const* d_in, const int* in_sizes, int n_in,
                              void* d_out, int out_size) {
    (void)in_sizes; (void)n_in; (void)out_size;
    const float* x_vq  = (const float*)d_in[0];
    const float* w_off = (const float*)d_in[1];
    const float* b_off = (const float*)d_in[2];
    const float* w_co  = (const float*)d_in[3];
    const float* b_co  = (const float*)d_in[4];
    const float* w_dcn = (const float*)d_in[5];
    const float* b_dcn = (const float*)d_in[6];
    float* out = (float*)d_out;

    cudaFuncSetAttribute(conv_mma_kernel<OC1, 0>, cudaFuncAttributeMaxDynamicSharedMemorySize, CONV_SMEM);
    cudaFuncSetAttribute(conv_mma_kernel<OC2, 1>, cudaFuncAttributeMaxDynamicSharedMemorySize, CONV_SMEM);

    prep_wA_kernel<<<(9 * 4 * 128 * 32 + 255) / 256, 256>>>(w_off, OC1, 0);
    prep_wA_kernel<<<(9 * 4 * 128 * 32 + 255) / 256, 256>>>(w_co,  OC2, 1);
    prep_wd_kernel<<<(36 * 128 * 32 + 255) / 256, 256>>>(w_dcn);

    dim3 cgrid(72, BATCH);   // 3x24 tiles of 32x4 px, 128 oc per CTA
    conv_mma_kernel<OC1, 0><<<cgrid, 256, CONV_SMEM>>>(x_vq, b_off);
    conv_mma_kernel<OC2, 1><<<cgrid, 256, CONV_SMEM>>>(nullptr, b_co);

    dim3 dgrid(3 * 48, BATCH);  // 32x2 px tiles
    dcn_mma_kernel<<<dgrid, 256>>>(x_vq, b_dcn, out);
}

// round 7
// speedup vs baseline: 2.0455x; 1.0808x over previous
#include <cuda_runtime.h>
#include <cstdint>

#define CIN   128
#define HW    96
#define HWSZ  9216
#define BATCH 4
#define OC1   128
#define OC2   108
#define NDG   4

// ---------------- scratch (static device globals; no allocs) ----------------
__device__ float g_xres[BATCH * OC1 * HWSZ];     // conv1 output
__device__ float g_co  [BATCH * OC2 * HWSZ];     // conv2 output
__device__ float g_wA1 [9 * 4 * 128 * 32];       // conv1 W packed [k*4+icc][oc][j(perm icl)], tf32
__device__ float g_wA2 [9 * 4 * 128 * 32];       // conv2 W packed (oc>=108 zero)
__device__ float g_wd2 [36 * 128 * 32];          // dcn W packed [g*9+k][oc][j(perm icl)], tf32

// ---------------- helpers ----------------
__device__ __forceinline__ uint32_t tf32_bits(float x) {
    uint32_t r; asm("cvt.rna.tf32.f32 %0, %1;" : "=r"(r) : "f"(x)); return r;
}
__device__ __forceinline__ float to_tf32(float x) {
    return __uint_as_float(tf32_bits(x));
}
__device__ __forceinline__ void mma8(float c[4], const uint32_t a[4], const uint32_t b[2]) {
    asm volatile("mma.sync.aligned.m16n8k8.row.col.f32.tf32.tf32.f32 "
        "{%0,%1,%2,%3}, {%4,%5,%6,%7}, {%8,%9}, {%0,%1,%2,%3};"
        : "+f"(c[0]), "+f"(c[1]), "+f"(c[2]), "+f"(c[3])
        : "r"(a[0]), "r"(a[1]), "r"(a[2]), "r"(a[3]), "r"(b[0]), "r"(b[1]));
}
__device__ __forceinline__ uint32_t fbits(float x) { return __float_as_uint(x); }

// icl permutation: j -> icl, so that A-frag k-cols (lk, lk+4) are ADJACENT:
// j = s*8 + lk*2 + e  ->  icl = s*8 + lk + 4*e
__device__ __forceinline__ int perm_icl(int j) {
    return (j & ~7) + ((j & 7) >> 1) + 4 * (j & 1);
}

// ---------------- weight prep ----------------
// conv: dst[(k*4+icc)*4096 + oc*32 + j] = tf32(w[oc][icc*32+perm(j)][k])
__global__ void prep_wA_kernel(const float* __restrict__ w, int OC, int which) {
    float* dst = which ? g_wA2 : g_wA1;
    int i = blockIdx.x * 256 + threadIdx.x;
    if (i >= 9 * 4 * 128 * 32) return;
    int j = i & 31, oc = (i >> 5) & 127, icc = (i >> 12) & 3, k = i >> 14;
    int ic = icc * 32 + perm_icl(j);
    float v = (oc < OC) ? w[(oc * CIN + ic) * 9 + k] : 0.f;
    dst[i] = to_tf32(v);
}
// dcn: dst[(g*9+k)*4096 + oc*32 + j] = tf32(w[oc][g*32+perm(j)][k])
__global__ void prep_wd_kernel(const float* __restrict__ w) {
    int i = blockIdx.x * 256 + threadIdx.x;
    if (i >= 36 * 128 * 32) return;
    int j = i & 31, oc = (i >> 5) & 127, chunk = i >> 12;
    int g = chunk / 9, k = chunk % 9;
    g_wd2[i] = to_tf32(w[(oc * CIN + g * 32 + perm_icl(j)) * 9 + k]);
}

// ---------------- tf32 mma conv3x3 ----------------
// CTA: 256 thr = 8 warps (2 M x 4 N). Tile M=128 oc, N=128 px (32x4 spatial).
// Warp tile 64x32 -> 4 mtiles x 4 ntiles of m16n8k8, K=1152 as 144 k8-steps.
#define STG_S 232
#define SW_S  36
#define CONV_SMEM ((32*STG_S + 2*128*SW_S) * 4)   // 66560 B

template<int OC, int MODE>
__global__ void __launch_bounds__(256, 2) conv_mma_kernel(const float* __restrict__ xin,
                                                          const float* __restrict__ bias) {
    extern __shared__ float sm[];
    float* stg = sm;                         // 32*232
    float* swb0 = sm + 32 * STG_S;           // 128*36
    float* swb1 = swb0 + 128 * SW_S;

    const float* x  = (MODE == 0) ? xin : g_xres;
    const float* wA = (MODE == 0) ? g_wA1 : g_wA2;
    float*       y  = (MODE == 0) ? g_xres : g_co;

    const int tid = threadIdx.x;
    const int wid = tid >> 5, lane = tid & 31;
    const int warp_m = wid >> 2, warp_n = wid & 3;
    const int lm = lane >> 2, lk = lane & 3;
    const int b = blockIdx.y;
    const int tile_x = (blockIdx.x % 3) * 32;
    const int tile_y = (blockIdx.x / 3) * 4;

    float c[4][4][4];
#pragma unroll
    for (int mt = 0; mt < 4; mt++)
#pragma unroll
        for (int nt = 0; nt < 4; nt++)
#pragma unroll
            for (int i = 0; i < 4; i++) c[mt][nt][i] = 0.f;

    int pxbase[4], arow[4];
#pragma unroll
    for (int nt = 0; nt < 4; nt++) {
        int px = warp_n * 32 + nt * 8 + lm;
        pxbase[nt] = (px >> 5) * 34 + (px & 31);
    }
#pragma unroll
    for (int mt = 0; mt < 4; mt++)
        arow[mt] = (warp_m * 64 + mt * 16 + lm) * SW_S;

    const float* xb = x + (size_t)b * CIN * HWSZ;

    for (int icc = 0; icc < 4; icc++) {
        __syncthreads();   // prior compute done reading stg/s_w
        for (int i = tid; i < 32 * 204; i += 256) {
            int ic = i / 204, rem = i % 204;
            int r = rem / 34, cc = rem % 34;
            int gy = tile_y + r - 1, gx = tile_x + cc - 1;
            float v = 0.f;
            if (gy >= 0 && gy < HW && gx >= 0 && gx < HW)
                v = xb[(size_t)(icc * 32 + ic) * HWSZ + gy * HW + gx];
            stg[ic * STG_S + r * 34 + cc] = to_tf32(v);
        }
        {
            const float* Asrc = wA + (size_t)(0 * 4 + icc) * 4096;
#pragma unroll
            for (int j = 0; j < 16; j++) {
                int i = tid + j * 256;
                swb0[(i >> 5) * SW_S + (i & 31)] = Asrc[i];
            }
        }
        __syncthreads();

        for (int k = 0; k < 9; k++) {
            float* swc = (k & 1) ? swb1 : swb0;
            float* swn = (k & 1) ? swb0 : swb1;
            if (k < 8) {
                const float* Asrc = wA + (size_t)((k + 1) * 4 + icc) * 4096;
#pragma unroll
                for (int j = 0; j < 16; j++) {
                    int i = tid + j * 256;
                    swn[(i >> 5) * SW_S + (i & 31)] = Asrc[i];
                }
            }
            const int koff = (k / 3) * 34 + (k % 3);
#pragma unroll
            for (int s = 0; s < 4; s++) {
                uint32_t A[4][4], B[4][2];
#pragma unroll
                for (int mt = 0; mt < 4; mt++) {
                    // permuted layout: (lk, lk+4) adjacent -> two LDS.64
                    const float* ap = swc + arow[mt] + s * 8 + lk * 2;
                    float2 f0 = *reinterpret_cast<const float2*>(ap);
                    float2 f1 = *reinterpret_cast<const float2*>(ap + 8 * SW_S);
                    A[mt][0] = fbits(f0.x); A[mt][2] = fbits(f0.y);
                    A[mt][1] = fbits(f1.x); A[mt][3] = fbits(f1.y);
                }
#pragma unroll
                for (int nt = 0; nt < 4; nt++) {
                    const float* bp = stg + (s * 8 + lk) * STG_S + pxbase[nt] + koff;
                    B[nt][0] = fbits(bp[0]);
                    B[nt][1] = fbits(bp[4 * STG_S]);
                }
#pragma unroll
                for (int mt = 0; mt < 4; mt++)
#pragma unroll
                    for (int nt = 0; nt < 4; nt++)
                        mma8(c[mt][nt], A[mt], B[nt]);
            }
            __syncthreads();
        }
    }

    // epilogue
#pragma unroll
    for (int mt = 0; mt < 4; mt++) {
        int oc0 = warp_m * 64 + mt * 16 + lm;
        int oc1 = oc0 + 8;
#pragma unroll
        for (int nt = 0; nt < 4; nt++) {
            int px0 = warp_n * 32 + nt * 8 + lk * 2;
            int gy = tile_y + (px0 >> 5), gx = tile_x + (px0 & 31);
            if (oc0 < OC) {
                float bz = bias[oc0];
                float2 o = make_float2(c[mt][nt][0] + bz, c[mt][nt][1] + bz);
                *reinterpret_cast<float2*>(&y[((size_t)(b * OC + oc0)) * HWSZ + gy * HW + gx]) = o;
            }
            if (oc1 < OC) {
                float bz = bias[oc1];
                float2 o = make_float2(c[mt][nt][2] + bz, c[mt][nt][3] + bz);
                *reinterpret_cast<float2*>(&y[((size_t)(b * OC + oc1)) * HWSZ + gy * HW + gx]) = o;
            }
        }
    }
}

// ---------------- modulated deformable conv (gather + tf32 mma GEMM) ----------------
// CTA: 256 thr = 8 warps (2 M x 4 N). Tile M=128 oc, N=128 px (32x4 spatial).
// Per (g,k): phase A bilinear params (2 corners/thread), phase B gather col[32][136],
// phase C mma identical structure to conv (warp tile 64x32, 4 s-steps).
#define COL_S 136
#define DCN_SMEM ((2*128*SW_S + 32*COL_S + 128*4) * 4 + 128*4*4)  // 36864+17408+2048+2048 = 58368

__global__ void __launch_bounds__(256, 2) dcn_mma_kernel(const float* __restrict__ x,
                                                         const float* __restrict__ bias,
                                                         float* __restrict__ y) {
    extern __shared__ float sm[];
    float* s_w0  = sm;                       // 128*36
    float* s_w1  = s_w0 + 128 * SW_S;
    float* s_col = s_w1 + 128 * SW_S;        // 32*136
    float* s_wgt = s_col + 32 * COL_S;       // [128][4]
    int*   s_idx = (int*)(s_wgt + 128 * 4);  // [128][4]

    const int tid = threadIdx.x;
    const int wid = tid >> 5, lane = tid & 31;
    const int warp_m = wid >> 2, warp_n = wid & 3;
    const int lm = lane >> 2, lk = lane & 3;
    const int b = blockIdx.y;
    const int tile_x = (blockIdx.x % 3) * 32;
    const int tile_y = (blockIdx.x / 3) * 4;

    float c[4][4][4];
#pragma unroll
    for (int mt = 0; mt < 4; mt++)
#pragma unroll
        for (int nt = 0; nt < 4; nt++)
#pragma unroll
            for (int i = 0; i < 4; i++) c[mt][nt][i] = 0.f;

    int pxidx[4], arow[4];
#pragma unroll
    for (int nt = 0; nt < 4; nt++)
        pxidx[nt] = warp_n * 32 + nt * 8 + lm;
#pragma unroll
    for (int mt = 0; mt < 4; mt++)
        arow[mt] = (warp_m * 64 + mt * 16 + lm) * SW_S;

    const float* cob = g_co + (size_t)b * OC2 * HWSZ;
    const float* xb  = x    + (size_t)b * CIN * HWSZ;

    // preload chunk 0
#pragma unroll
    for (int j = 0; j < 16; j++) {
        int i = tid + j * 256;
        s_w0[(i >> 5) * SW_S + (i & 31)] = g_wd2[i];
    }

    int it = 0;
    for (int g = 0; g < NDG; g++) {
        for (int k = 0; k < 9; k++, it++) {
            const int buf = it & 1;
            // phase A: 2 corners per thread (px = tid>>1)
            {
                int px = tid >> 1, half = tid & 1;
                int gy = tile_y + (px >> 5), gx = tile_x + (px & 31);
                int c_y = g * 18 + 2 * k;
                const float* basep = cob + gy * HW + gx;
                float offy = basep[(size_t)c_y * HWSZ];
                float offx = basep[(size_t)(c_y + 1) * HWSZ];
                float mraw = basep[(size_t)(72 + g * 9 + k) * HWSZ];
                float m  = 1.f / (1.f + __expf(-mraw));
                float ys = (float)gy + (float)(k / 3 - 1) + offy;
                float xs = (float)gx + (float)(k % 3 - 1) + offx;
                float y0f = floorf(ys), x0f = floorf(xs);
                float fy = ys - y0f, fx = xs - x0f;
                int y0 = (int)y0f, x0 = (int)x0f;
#pragma unroll
                for (int cc = 0; cc < 2; cc++) {
                    int cnr = 2 * half + cc;
                    int dy = cnr >> 1, dx = cnr & 1;
                    int yi = y0 + dy, xi = x0 + dx;
                    bool valid = (yi >= 0) && (yi < HW) && (xi >= 0) && (xi < HW);
                    float wy = dy ? fy : (1.f - fy);
                    float wx = dx ? fx : (1.f - fx);
                    int yc = min(max(yi, 0), HW - 1);
                    int xc = min(max(xi, 0), HW - 1);
                    s_idx[px * 4 + cnr] = yc * HW + xc;
                    s_wgt[px * 4 + cnr] = valid ? (wy * wx * m) : 0.f;
                }
            }
            // prefetch next weight chunk
            if (it < 35) {
                const float* Wn = g_wd2 + (size_t)(it + 1) * 4096;
                float* swn = buf ? s_w0 : s_w1;
#pragma unroll
                for (int j = 0; j < 16; j++) {
                    int i = tid + j * 256;
                    swn[(i >> 5) * SW_S + (i & 31)] = Wn[i];
                }
            }
            __syncthreads();

            // phase B: gather col[ic][px] (tf32), 16 elems/thread, 64 LDG in flight
#pragma unroll
            for (int j = 0; j < 16; j++) {
                int e = tid + j * 256;
                int ic = e >> 7, px = e & 127;
                const float* xp = xb + (size_t)(g * 32 + ic) * HWSZ;
                float v = s_wgt[px * 4 + 0] * __ldg(xp + s_idx[px * 4 + 0])
                        + s_wgt[px * 4 + 1] * __ldg(xp + s_idx[px * 4 + 1])
                        + s_wgt[px * 4 + 2] * __ldg(xp + s_idx[px * 4 + 2])
                        + s_wgt[px * 4 + 3] * __ldg(xp + s_idx[px * 4 + 3]);
                s_col[ic * COL_S + px] = to_tf32(v);
            }
            __syncthreads();

            // phase C: mma (warp tile 64x32)
            const float* swc = buf ? s_w1 : s_w0;
#pragma unroll
            for (int s = 0; s < 4; s++) {
                uint32_t A[4][4], B[4][2];
#pragma unroll
                for (int mt = 0; mt < 4; mt++) {
                    const float* ap = swc + arow[mt] + s * 8 + lk * 2;
                    float2 f0 = *reinterpret_cast<const float2*>(ap);
                    float2 f1 = *reinterpret_cast<const float2*>(ap + 8 * SW_S);
                    A[mt][0] = fbits(f0.x); A[mt][2] = fbits(f0.y);
                    A[mt][1] = fbits(f1.x); A[mt][3] = fbits(f1.y);
                }
#pragma unroll
                for (int nt = 0; nt < 4; nt++) {
                    const float* bp = s_col + (s * 8 + lk) * COL_S + pxidx[nt];
                    B[nt][0] = fbits(bp[0]);
                    B[nt][1] = fbits(bp[4 * COL_S]);
                }
#pragma unroll
                for (int mt = 0; mt < 4; mt++)
#pragma unroll
                    for (int nt = 0; nt < 4; nt++)
                        mma8(c[mt][nt], A[mt], B[nt]);
            }
            __syncthreads();
        }
    }

    // epilogue
#pragma unroll
    for (int mt = 0; mt < 4; mt++) {
        int oc0 = warp_m * 64 + mt * 16 + lm;
        int oc1 = oc0 + 8;
        float bz0 = bias[oc0], bz1 = bias[oc1];
#pragma unroll
        for (int nt = 0; nt < 4; nt++) {
            int px0 = warp_n * 32 + nt * 8 + lk * 2;
            int gy = tile_y + (px0 >> 5), gx = tile_x + (px0 & 31);
            *reinterpret_cast<float2*>(&y[((size_t)(b * OC1 + oc0)) * HWSZ + gy * HW + gx]) =
                make_float2(c[mt][nt][0] + bz0, c[mt][nt][1] + bz0);
            *reinterpret_cast<float2*>(&y[((size_t)(b * OC1 + oc1)) * HWSZ + gy * HW + gx]) =
                make_float2(c[mt][nt][2] + bz1, c[mt][nt][3] + bz1);
        }
    }
}

// ---------------- launch ----------------
extern "C" void kernel_launch(void* const* d_in, const int* in_sizes, int n_in,
                              void* d_out, int out_size) {
    (void)in_sizes; (void)n_in; (void)out_size;
    const float* x_vq  = (const float*)d_in[0];
    const float* w_off = (const float*)d_in[1];
    const float* b_off = (const float*)d_in[2];
    const float* w_co  = (const float*)d_in[3];
    const float* b_co  = (const float*)d_in[4];
    const float* w_dcn = (const float*)d_in[5];
    const float* b_dcn = (const float*)d_in[6];
    float* out = (float*)d_out;

    cudaFuncSetAttribute(conv_mma_kernel<OC1, 0>, cudaFuncAttributeMaxDynamicSharedMemorySize, CONV_SMEM);
    cudaFuncSetAttribute(conv_mma_kernel<OC2, 1>, cudaFuncAttributeMaxDynamicSharedMemorySize, CONV_SMEM);
    cudaFuncSetAttribute(dcn_mma_kernel, cudaFuncAttributeMaxDynamicSharedMemorySize, DCN_SMEM);

    prep_wA_kernel<<<(9 * 4 * 128 * 32 + 255) / 256, 256>>>(w_off, OC1, 0);
    prep_wA_kernel<<<(9 * 4 * 128 * 32 + 255) / 256, 256>>>(w_co,  OC2, 1);
    prep_wd_kernel<<<(36 * 128 * 32 + 255) / 256, 256>>>(w_dcn);

    dim3 cgrid(72, BATCH);   // 3x24 tiles of 32x4 px, 128 oc per CTA
    conv_mma_kernel<OC1, 0><<<cgrid, 256, CONV_SMEM>>>(x_vq, b_off);
    conv_mma_kernel<OC2, 1><<<cgrid, 256, CONV_SMEM>>>(nullptr, b_co);

    dim3 dgrid(72, BATCH);   // 3x24 tiles of 32x4 px
    dcn_mma_kernel<<<dgrid, 256, DCN_SMEM>>>(x_vq, b_dcn, out);
}

// round 8
// speedup vs baseline: 2.1077x; 1.0304x over previous
#include <cuda_runtime.h>
#include <cstdint>

#define CIN   128
#define HW    96
#define HWSZ  9216
#define BATCH 4
#define OC1   128
#define OC2   108
#define NDG   4

// ---------------- scratch (static device globals; no allocs) ----------------
__device__ float g_xres[BATCH * OC1 * HWSZ];     // conv1 output
__device__ float g_co  [BATCH * OC2 * HWSZ];     // conv2 output
__device__ float g_wA1 [9 * 4 * 128 * 32];       // conv1 W [k*4+icc][oc][icl] (UNpermuted), tf32
__device__ float g_wA2 [9 * 4 * 128 * 32];       // conv2 W (oc>=108 zero)
__device__ float g_wd2 [36 * 128 * 32];          // dcn W [g*9+k][oc][j(perm icl)], tf32

// ---------------- helpers ----------------
__device__ __forceinline__ uint32_t tf32_bits(float x) {
    uint32_t r; asm("cvt.rna.tf32.f32 %0, %1;" : "=r"(r) : "f"(x)); return r;
}
__device__ __forceinline__ float to_tf32(float x) {
    return __uint_as_float(tf32_bits(x));
}
__device__ __forceinline__ void mma8(float c[4], const uint32_t a[4], const uint32_t b[2]) {
    asm volatile("mma.sync.aligned.m16n8k8.row.col.f32.tf32.tf32.f32 "
        "{%0,%1,%2,%3}, {%4,%5,%6,%7}, {%8,%9}, {%0,%1,%2,%3};"
        : "+f"(c[0]), "+f"(c[1]), "+f"(c[2]), "+f"(c[3])
        : "r"(a[0]), "r"(a[1]), "r"(a[2]), "r"(a[3]), "r"(b[0]), "r"(b[1]));
}
__device__ __forceinline__ uint32_t fbits(float x) { return __float_as_uint(x); }

// icl permutation for DCN A-pair loads: j = s*8 + lk*2 + e -> icl = s*8 + lk + 4*e
__device__ __forceinline__ int perm_icl(int j) {
    return (j & ~7) + ((j & 7) >> 1) + 4 * (j & 1);
}

// ---------------- weight prep ----------------
// conv (UNpermuted; scalar conflict-free A loads): dst[(k*4+icc)*4096 + oc*32 + icl]
__global__ void prep_wA_kernel(const float* __restrict__ w, int OC, int which) {
    float* dst = which ? g_wA2 : g_wA1;
    int i = blockIdx.x * 256 + threadIdx.x;
    if (i >= 9 * 4 * 128 * 32) return;
    int icl = i & 31, oc = (i >> 5) & 127, icc = (i >> 12) & 3, k = i >> 14;
    int ic = icc * 32 + icl;
    float v = (oc < OC) ? w[(oc * CIN + ic) * 9 + k] : 0.f;
    dst[i] = to_tf32(v);
}
// dcn (permuted for float2 A loads): dst[(g*9+k)*4096 + oc*32 + j]
__global__ void prep_wd_kernel(const float* __restrict__ w) {
    int i = blockIdx.x * 256 + threadIdx.x;
    if (i >= 36 * 128 * 32) return;
    int j = i & 31, oc = (i >> 5) & 127, chunk = i >> 12;
    int g = chunk / 9, k = chunk % 9;
    g_wd2[i] = to_tf32(w[(oc * CIN + g * 32 + perm_icl(j)) * 9 + k]);
}

// ---------------- tf32 mma conv3x3 ----------------
// CTA: 256 thr = 8 warps (2 M x 4 N). Tile M=128 oc, N=128 px (32x4 spatial).
// B staged as K-PAIRED float2: stg2[pair = s*4+lk][r*34+c] = (ch s*8+lk, ch s*8+lk+4)
// -> one LDS.64 per B frag, 2-phase conflict-optimal (pair stride 216: 216%16=8).
// A loads scalar (bank = 4lm+lk, conflict-free).
#define PAIR_S 216
#define SW_S   36
#define CONV_SMEM ((16*PAIR_S*2 + 2*128*SW_S) * 4)   // 27648 + 36864 = 64512 B

template<int OC, int MODE>
__global__ void __launch_bounds__(256, 2) conv_mma_kernel(const float* __restrict__ xin,
                                                          const float* __restrict__ bias) {
    extern __shared__ float sm[];
    float2* stg2 = (float2*)sm;              // [16][216]
    float* swb0 = sm + 16 * PAIR_S * 2;      // 128*36
    float* swb1 = swb0 + 128 * SW_S;

    const float* x  = (MODE == 0) ? xin : g_xres;
    const float* wA = (MODE == 0) ? g_wA1 : g_wA2;
    float*       y  = (MODE == 0) ? g_xres : g_co;

    const int tid = threadIdx.x;
    const int wid = tid >> 5, lane = tid & 31;
    const int warp_m = wid >> 2, warp_n = wid & 3;
    const int lm = lane >> 2, lk = lane & 3;
    const int b = blockIdx.y;
    const int tile_x = (blockIdx.x % 3) * 32;
    const int tile_y = (blockIdx.x / 3) * 4;

    float c[4][4][4];
#pragma unroll
    for (int mt = 0; mt < 4; mt++)
#pragma unroll
        for (int nt = 0; nt < 4; nt++)
#pragma unroll
            for (int i = 0; i < 4; i++) c[mt][nt][i] = 0.f;

    int pxbase[4], arow[4];
#pragma unroll
    for (int nt = 0; nt < 4; nt++) {
        int px = warp_n * 32 + nt * 8 + lm;
        pxbase[nt] = (px >> 5) * 34 + (px & 31);
    }
#pragma unroll
    for (int mt = 0; mt < 4; mt++)
        arow[mt] = (warp_m * 64 + mt * 16 + lm) * SW_S;

    const float* xb = x + (size_t)b * CIN * HWSZ;

    for (int icc = 0; icc < 4; icc++) {
        __syncthreads();   // prior compute done reading stg2/s_w
        // stage input chunk as k-paired float2: pair p=s*4+lk -> channels (s*8+lk, +4)
        for (int i = tid; i < 16 * 204; i += 256) {
            int p = i / 204, rem = i % 204;
            int r = rem / 34, cc = rem % 34;
            int s = p >> 2, plk = p & 3;
            int ic1 = icc * 32 + s * 8 + plk;
            int gy = tile_y + r - 1, gx = tile_x + cc - 1;
            float v1 = 0.f, v2 = 0.f;
            if (gy >= 0 && gy < HW && gx >= 0 && gx < HW) {
                const float* px0 = xb + (size_t)ic1 * HWSZ + gy * HW + gx;
                v1 = px0[0];
                v2 = px0[4 * HWSZ];
            }
            stg2[p * PAIR_S + rem] = make_float2(to_tf32(v1), to_tf32(v2));
        }
        {
            const float* Asrc = wA + (size_t)(0 * 4 + icc) * 4096;
#pragma unroll
            for (int j = 0; j < 16; j++) {
                int i = tid + j * 256;
                swb0[(i >> 5) * SW_S + (i & 31)] = Asrc[i];
            }
        }
        __syncthreads();

        for (int k = 0; k < 9; k++) {
            float* swc = (k & 1) ? swb1 : swb0;
            float* swn = (k & 1) ? swb0 : swb1;
            if (k < 8) {
                const float* Asrc = wA + (size_t)((k + 1) * 4 + icc) * 4096;
#pragma unroll
                for (int j = 0; j < 16; j++) {
                    int i = tid + j * 256;
                    swn[(i >> 5) * SW_S + (i & 31)] = Asrc[i];
                }
            }
            const int koff = (k / 3) * 34 + (k % 3);
#pragma unroll
            for (int s = 0; s < 4; s++) {
                uint32_t A[4][4], B[4][2];
#pragma unroll
                for (int mt = 0; mt < 4; mt++) {
                    const float* ap = swc + arow[mt] + s * 8 + lk;   // bank 4lm+lk: conflict-free
                    A[mt][0] = fbits(ap[0]);
                    A[mt][1] = fbits(ap[8 * SW_S]);
                    A[mt][2] = fbits(ap[4]);
                    A[mt][3] = fbits(ap[8 * SW_S + 4]);
                }
#pragma unroll
                for (int nt = 0; nt < 4; nt++) {
                    float2 f = stg2[(s * 4 + lk) * PAIR_S + pxbase[nt] + koff];
                    B[nt][0] = fbits(f.x);
                    B[nt][1] = fbits(f.y);
                }
#pragma unroll
                for (int mt = 0; mt < 4; mt++)
#pragma unroll
                    for (int nt = 0; nt < 4; nt++)
                        mma8(c[mt][nt], A[mt], B[nt]);
            }
            __syncthreads();
        }
    }

    // epilogue
#pragma unroll
    for (int mt = 0; mt < 4; mt++) {
        int oc0 = warp_m * 64 + mt * 16 + lm;
        int oc1 = oc0 + 8;
#pragma unroll
        for (int nt = 0; nt < 4; nt++) {
            int px0 = warp_n * 32 + nt * 8 + lk * 2;
            int gy = tile_y + (px0 >> 5), gx = tile_x + (px0 & 31);
            if (oc0 < OC) {
                float bz = bias[oc0];
                float2 o = make_float2(c[mt][nt][0] + bz, c[mt][nt][1] + bz);
                *reinterpret_cast<float2*>(&y[((size_t)(b * OC + oc0)) * HWSZ + gy * HW + gx]) = o;
            }
            if (oc1 < OC) {
                float bz = bias[oc1];
                float2 o = make_float2(c[mt][nt][2] + bz, c[mt][nt][3] + bz);
                *reinterpret_cast<float2*>(&y[((size_t)(b * OC + oc1)) * HWSZ + gy * HW + gx]) = o;
            }
        }
    }
}

// ---------------- modulated deformable conv (unchanged from R7 measured-good) ----------------
#define COL_S 136
#define DCN_SMEM ((2*128*SW_S + 32*COL_S + 128*4) * 4 + 128*4*4)  // 58368

__global__ void __launch_bounds__(256, 2) dcn_mma_kernel(const float* __restrict__ x,
                                                         const float* __restrict__ bias,
                                                         float* __restrict__ y) {
    extern __shared__ float sm[];
    float* s_w0  = sm;                       // 128*36
    float* s_w1  = s_w0 + 128 * SW_S;
    float* s_col = s_w1 + 128 * SW_S;        // 32*136
    float* s_wgt = s_col + 32 * COL_S;       // [128][4]
    int*   s_idx = (int*)(s_wgt + 128 * 4);  // [128][4]

    const int tid = threadIdx.x;
    const int wid = tid >> 5, lane = tid & 31;
    const int warp_m = wid >> 2, warp_n = wid & 3;
    const int lm = lane >> 2, lk = lane & 3;
    const int b = blockIdx.y;
    const int tile_x = (blockIdx.x % 3) * 32;
    const int tile_y = (blockIdx.x / 3) * 4;

    float c[4][4][4];
#pragma unroll
    for (int mt = 0; mt < 4; mt++)
#pragma unroll
        for (int nt = 0; nt < 4; nt++)
#pragma unroll
            for (int i = 0; i < 4; i++) c[mt][nt][i] = 0.f;

    int pxidx[4], arow[4];
#pragma unroll
    for (int nt = 0; nt < 4; nt++)
        pxidx[nt] = warp_n * 32 + nt * 8 + lm;
#pragma unroll
    for (int mt = 0; mt < 4; mt++)
        arow[mt] = (warp_m * 64 + mt * 16 + lm) * SW_S;

    const float* cob = g_co + (size_t)b * OC2 * HWSZ;
    const float* xb  = x    + (size_t)b * CIN * HWSZ;

    // preload chunk 0
#pragma unroll
    for (int j = 0; j < 16; j++) {
        int i = tid + j * 256;
        s_w0[(i >> 5) * SW_S + (i & 31)] = g_wd2[i];
    }

    int it = 0;
    for (int g = 0; g < NDG; g++) {
        for (int k = 0; k < 9; k++, it++) {
            const int buf = it & 1;
            // phase A: 2 corners per thread (px = tid>>1)
            {
                int px = tid >> 1, half = tid & 1;
                int gy = tile_y + (px >> 5), gx = tile_x + (px & 31);
                int c_y = g * 18 + 2 * k;
                const float* basep = cob + gy * HW + gx;
                float offy = basep[(size_t)c_y * HWSZ];
                float offx = basep[(size_t)(c_y + 1) * HWSZ];
                float mraw = basep[(size_t)(72 + g * 9 + k) * HWSZ];
                float m  = 1.f / (1.f + __expf(-mraw));
                float ys = (float)gy + (float)(k / 3 - 1) + offy;
                float xs = (float)gx + (float)(k % 3 - 1) + offx;
                float y0f = floorf(ys), x0f = floorf(xs);
                float fy = ys - y0f, fx = xs - x0f;
                int y0 = (int)y0f, x0 = (int)x0f;
#pragma unroll
                for (int cc = 0; cc < 2; cc++) {
                    int cnr = 2 * half + cc;
                    int dy = cnr >> 1, dx = cnr & 1;
                    int yi = y0 + dy, xi = x0 + dx;
                    bool valid = (yi >= 0) && (yi < HW) && (xi >= 0) && (xi < HW);
                    float wy = dy ? fy : (1.f - fy);
                    float wx = dx ? fx : (1.f - fx);
                    int yc = min(max(yi, 0), HW - 1);
                    int xc = min(max(xi, 0), HW - 1);
                    s_idx[px * 4 + cnr] = yc * HW + xc;
                    s_wgt[px * 4 + cnr] = valid ? (wy * wx * m) : 0.f;
                }
            }
            // prefetch next weight chunk
            if (it < 35) {
                const float* Wn = g_wd2 + (size_t)(it + 1) * 4096;
                float* swn = buf ? s_w0 : s_w1;
#pragma unroll
                for (int j = 0; j < 16; j++) {
                    int i = tid + j * 256;
                    swn[(i >> 5) * SW_S + (i & 31)] = Wn[i];
                }
            }
            __syncthreads();

            // phase B: gather col[ic][px] (tf32), 16 elems/thread
#pragma unroll
            for (int j = 0; j < 16; j++) {
                int e = tid + j * 256;
                int ic = e >> 7, px = e & 127;
                const float* xp = xb + (size_t)(g * 32 + ic) * HWSZ;
                float v = s_wgt[px * 4 + 0] * __ldg(xp + s_idx[px * 4 + 0])
                        + s_wgt[px * 4 + 1] * __ldg(xp + s_idx[px * 4 + 1])
                        + s_wgt[px * 4 + 2] * __ldg(xp + s_idx[px * 4 + 2])
                        + s_wgt[px * 4 + 3] * __ldg(xp + s_idx[px * 4 + 3]);
                s_col[ic * COL_S + px] = to_tf32(v);
            }
            __syncthreads();

            // phase C: mma (warp tile 64x32)
            const float* swc = buf ? s_w1 : s_w0;
#pragma unroll
            for (int s = 0; s < 4; s++) {
                uint32_t A[4][4], B[4][2];
#pragma unroll
                for (int mt = 0; mt < 4; mt++) {
                    const float* ap = swc + arow[mt] + s * 8 + lk * 2;
                    float2 f0 = *reinterpret_cast<const float2*>(ap);
                    float2 f1 = *reinterpret_cast<const float2*>(ap + 8 * SW_S);
                    A[mt][0] = fbits(f0.x); A[mt][2] = fbits(f0.y);
                    A[mt][1] = fbits(f1.x); A[mt][3] = fbits(f1.y);
                }
#pragma unroll
                for (int nt = 0; nt < 4; nt++) {
                    const float* bp = s_col + (s * 8 + lk) * COL_S + pxidx[nt];
                    B[nt][0] = fbits(bp[0]);
                    B[nt][1] = fbits(bp[4 * COL_S]);
                }
#pragma unroll
                for (int mt = 0; mt < 4; mt++)
#pragma unroll
                    for (int nt = 0; nt < 4; nt++)
                        mma8(c[mt][nt], A[mt], B[nt]);
            }
            __syncthreads();
        }
    }

    // epilogue
#pragma unroll
    for (int mt = 0; mt < 4; mt++) {
        int oc0 = warp_m * 64 + mt * 16 + lm;
        int oc1 = oc0 + 8;
        float bz0 = bias[oc0], bz1 = bias[oc1];
#pragma unroll
        for (int nt = 0; nt < 4; nt++) {
            int px0 = warp_n * 32 + nt * 8 + lk * 2;
            int gy = tile_y + (px0 >> 5), gx = tile_x + (px0 & 31);
            *reinterpret_cast<float2*>(&y[((size_t)(b * OC1 + oc0)) * HWSZ + gy * HW + gx]) =
                make_float2(c[mt][nt][0] + bz0, c[mt][nt][1] + bz0);
            *reinterpret_cast<float2*>(&y[((size_t)(b * OC1 + oc1)) * HWSZ + gy * HW + gx]) =
                make_float2(c[mt][nt][2] + bz1, c[mt][nt][3] + bz1);
        }
    }
}

// ---------------- launch ----------------
extern "C" void kernel_launch(void* const* d_in, const int* in_sizes, int n_in,
                              void* d_out, int out_size) {
    (void)in_sizes; (void)n_in; (void)out_size;
    const float* x_vq  = (const float*)d_in[0];
    const float* w_off = (const float*)d_in[1];
    const float* b_off = (const float*)d_in[2];
    const float* w_co  = (const float*)d_in[3];
    const float* b_co  = (const float*)d_in[4];
    const float* w_dcn = (const float*)d_in[5];
    const float* b_dcn = (const float*)d_in[6];
    float* out = (float*)d_out;

    cudaFuncSetAttribute(conv_mma_kernel<OC1, 0>, cudaFuncAttributeMaxDynamicSharedMemorySize, CONV_SMEM);
    cudaFuncSetAttribute(conv_mma_kernel<OC2, 1>, cudaFuncAttributeMaxDynamicSharedMemorySize, CONV_SMEM);
    cudaFuncSetAttribute(dcn_mma_kernel, cudaFuncAttributeMaxDynamicSharedMemorySize, DCN_SMEM);

    prep_wA_kernel<<<(9 * 4 * 128 * 32 + 255) / 256, 256>>>(w_off, OC1, 0);
    prep_wA_kernel<<<(9 * 4 * 128 * 32 + 255) / 256, 256>>>(w_co,  OC2, 1);
    prep_wd_kernel<<<(36 * 128 * 32 + 255) / 256, 256>>>(w_dcn);

    dim3 cgrid(72, BATCH);   // 3x24 tiles of 32x4 px, 128 oc per CTA
    conv_mma_kernel<OC1, 0><<<cgrid, 256, CONV_SMEM>>>(x_vq, b_off);
    conv_mma_kernel<OC2, 1><<<cgrid, 256, CONV_SMEM>>>(nullptr, b_co);

    dim3 dgrid(72, BATCH);   // 3x24 tiles of 32x4 px
    dcn_mma_kernel<<<dgrid, 256, DCN_SMEM>>>(x_vq, b_dcn, out);
}

// round 9
// speedup vs baseline: 2.1660x; 1.0277x over previous
#include <cuda_runtime.h>
#include <cstdint>

#define CIN   128
#define HW    96
#define HWSZ  9216
#define BATCH 4
#define OC1   128
#define OC2   108
#define NDG   4

// ---------------- scratch (static device globals; no allocs) ----------------
__device__ float g_xres[BATCH * OC1 * HWSZ];     // conv1 output
__device__ float g_co  [BATCH * OC2 * HWSZ];     // conv2 output
__device__ float g_wA1 [36 * 128 * 32];          // conv1 W [icc*9+k][oc][icl], tf32
__device__ float g_wA2 [36 * 128 * 32];          // conv2 W (oc>=108 zero)
__device__ float g_wd2 [36 * 128 * 32];          // dcn  W [g*9+k][oc][j(perm icl)], tf32

// ---------------- helpers ----------------
__device__ __forceinline__ uint32_t tf32_bits(float x) {
    uint32_t r; asm("cvt.rna.tf32.f32 %0, %1;" : "=r"(r) : "f"(x)); return r;
}
__device__ __forceinline__ float to_tf32(float x) {
    return __uint_as_float(tf32_bits(x));
}
__device__ __forceinline__ void mma8(float c[4], const uint32_t a[4], const uint32_t b[2]) {
    asm volatile("mma.sync.aligned.m16n8k8.row.col.f32.tf32.tf32.f32 "
        "{%0,%1,%2,%3}, {%4,%5,%6,%7}, {%8,%9}, {%0,%1,%2,%3};"
        : "+f"(c[0]), "+f"(c[1]), "+f"(c[2]), "+f"(c[3])
        : "r"(a[0]), "r"(a[1]), "r"(a[2]), "r"(a[3]), "r"(b[0]), "r"(b[1]));
}
__device__ __forceinline__ uint32_t fbits(float x) { return __float_as_uint(x); }

// icl permutation for DCN A-pair loads: j = s*8 + lk*2 + e -> icl = s*8 + lk + 4*e
__device__ __forceinline__ int perm_icl(int j) {
    return (j & ~7) + ((j & 7) >> 1) + 4 * (j & 1);
}

#define SW_S   36
#define WCH    4608      // floats per weight chunk in smem (128*36)

// float4 prefetch of one 4096-float chunk into padded smem [oc][36]
__device__ __forceinline__ void prefetch_chunk(float* dstb, const float* src, int tid) {
#pragma unroll
    for (int j = 0; j < 4; j++) {
        int t4 = tid + j * 256;
        float4 v = reinterpret_cast<const float4*>(src)[t4];
        *reinterpret_cast<float4*>(dstb + (t4 >> 3) * SW_S + (t4 & 7) * 4) = v;
    }
}

// ---------------- weight prep ----------------
// conv: chunk c = icc*9+k; dst[(c*128 + oc)*32 + icl] = tf32(w[oc][icc*32+icl][k])
__global__ void prep_wA_kernel(const float* __restrict__ w, int OC, int which) {
    float* dst = which ? g_wA2 : g_wA1;
    int i = blockIdx.x * 256 + threadIdx.x;
    if (i >= 36 * 128 * 32) return;
    int icl = i & 31, oc = (i >> 5) & 127, chunk = i >> 12;
    int icc = chunk / 9, k = chunk % 9;
    int ic = icc * 32 + icl;
    float v = (oc < OC) ? w[(oc * CIN + ic) * 9 + k] : 0.f;
    dst[i] = to_tf32(v);
}
// dcn (permuted for float2 A loads): dst[((g*9+k)*128 + oc)*32 + j]
__global__ void prep_wd_kernel(const float* __restrict__ w) {
    int i = blockIdx.x * 256 + threadIdx.x;
    if (i >= 36 * 128 * 32) return;
    int j = i & 31, oc = (i >> 5) & 127, chunk = i >> 12;
    int g = chunk / 9, k = chunk % 9;
    g_wd2[i] = to_tf32(w[(oc * CIN + g * 32 + perm_icl(j)) * 9 + k]);
}

// ---------------- tf32 mma conv3x3 ----------------
// CTA: 256 thr = 8 warps (2 M x 4 N). Tile M=128 oc, N=128 px (32x4 spatial).
// B staged as K-PAIRED float2 (one LDS.64/frag); A scalar (bank 4lm+lk conflict-free).
// 4 weight buffers, barrier every 2 taps; float4 prefetch.
#define PAIR_S 216
#define CONV_SMEM ((16*PAIR_S*2 + 4*WCH) * 4)   // 27648 + 73728 = 101376 B

__device__ __forceinline__ void conv_tap(float cacc[4][4][4], const float2* stg2,
                                         const float* swc, int koff,
                                         const int pxbase[4], const int arow[4], int lk) {
#pragma unroll
    for (int s = 0; s < 4; s++) {
        uint32_t A[4][4], B[4][2];
#pragma unroll
        for (int mt = 0; mt < 4; mt++) {
            const float* ap = swc + arow[mt] + s * 8 + lk;
            A[mt][0] = fbits(ap[0]);
            A[mt][1] = fbits(ap[8 * SW_S]);
            A[mt][2] = fbits(ap[4]);
            A[mt][3] = fbits(ap[8 * SW_S + 4]);
        }
#pragma unroll
        for (int nt = 0; nt < 4; nt++) {
            float2 f = stg2[(s * 4 + lk) * PAIR_S + pxbase[nt] + koff];
            B[nt][0] = fbits(f.x);
            B[nt][1] = fbits(f.y);
        }
#pragma unroll
        for (int mt = 0; mt < 4; mt++)
#pragma unroll
            for (int nt = 0; nt < 4; nt++)
                mma8(cacc[mt][nt], A[mt], B[nt]);
    }
}

template<int OC, int MODE>
__global__ void __launch_bounds__(256, 2) conv_mma_kernel(const float* __restrict__ xin,
                                                          const float* __restrict__ bias) {
    extern __shared__ float sm[];
    float2* stg2 = (float2*)sm;              // [16][216]
    float* swb = sm + 16 * PAIR_S * 2;       // 4 x 4608

    const float* x  = (MODE == 0) ? xin : g_xres;
    const float* wA = (MODE == 0) ? g_wA1 : g_wA2;
    float*       y  = (MODE == 0) ? g_xres : g_co;

    const int tid = threadIdx.x;
    const int wid = tid >> 5, lane = tid & 31;
    const int warp_m = wid >> 2, warp_n = wid & 3;
    const int lm = lane >> 2, lk = lane & 3;
    const int b = blockIdx.y;
    const int tile_x = (blockIdx.x % 3) * 32;
    const int tile_y = (blockIdx.x / 3) * 4;

    float cacc[4][4][4];
#pragma unroll
    for (int mt = 0; mt < 4; mt++)
#pragma unroll
        for (int nt = 0; nt < 4; nt++)
#pragma unroll
            for (int i = 0; i < 4; i++) cacc[mt][nt][i] = 0.f;

    int pxbase[4], arow[4];
#pragma unroll
    for (int nt = 0; nt < 4; nt++) {
        int px = warp_n * 32 + nt * 8 + lm;
        pxbase[nt] = (px >> 5) * 34 + (px & 31);
    }
#pragma unroll
    for (int mt = 0; mt < 4; mt++)
        arow[mt] = (warp_m * 64 + mt * 16 + lm) * SW_S;

    const float* xb = x + (size_t)b * CIN * HWSZ;

    // preload chunks 0,1
    prefetch_chunk(swb + 0 * WCH, wA + 0 * 4096, tid);
    prefetch_chunk(swb + 1 * WCH, wA + (size_t)1 * 4096, tid);

    int np = 2, c = 0;
    for (int icc = 0; icc < 4; icc++) {
        // stage input chunk as k-paired float2 (group-end barrier protects rewrite)
        for (int i = tid; i < 16 * 204; i += 256) {
            int p = i / 204, rem = i % 204;
            int r = rem / 34, cc2 = rem % 34;
            int s = p >> 2, plk = p & 3;
            int ic1 = icc * 32 + s * 8 + plk;
            int gy = tile_y + r - 1, gx = tile_x + cc2 - 1;
            float v1 = 0.f, v2 = 0.f;
            if (gy >= 0 && gy < HW && gx >= 0 && gx < HW) {
                const float* px0 = xb + (size_t)ic1 * HWSZ + gy * HW + gx;
                v1 = px0[0];
                v2 = px0[4 * HWSZ];
            }
            stg2[p * PAIR_S + rem] = make_float2(to_tf32(v1), to_tf32(v2));
        }
        __syncthreads();

        for (int k0 = 0; k0 < 9; k0 += 2) {
            // prefetch up to 2 chunks (credit rule: np <= c+3)
#pragma unroll
            for (int t = 0; t < 2; t++) {
                if (np <= c + 3 && np < 36) {
                    prefetch_chunk(swb + (np & 3) * WCH, wA + (size_t)np * 4096, tid);
                    np++;
                }
            }
            // compute 2 taps (1 for k0==8)
            {
                const int k = k0;
                conv_tap(cacc, stg2, swb + (c & 3) * WCH, (k / 3) * 34 + (k % 3), pxbase, arow, lk);
            }
            if (k0 < 8) {
                const int k = k0 + 1;
                conv_tap(cacc, stg2, swb + ((c + 1) & 3) * WCH, (k / 3) * 34 + (k % 3), pxbase, arow, lk);
                c += 2;
            } else {
                c += 1;
            }
            __syncthreads();
        }
    }

    // epilogue
#pragma unroll
    for (int mt = 0; mt < 4; mt++) {
        int oc0 = warp_m * 64 + mt * 16 + lm;
        int oc1 = oc0 + 8;
#pragma unroll
        for (int nt = 0; nt < 4; nt++) {
            int px0 = warp_n * 32 + nt * 8 + lk * 2;
            int gy = tile_y + (px0 >> 5), gx = tile_x + (px0 & 31);
            if (oc0 < OC) {
                float bz = bias[oc0];
                float2 o = make_float2(cacc[mt][nt][0] + bz, cacc[mt][nt][1] + bz);
                *reinterpret_cast<float2*>(&y[((size_t)(b * OC + oc0)) * HWSZ + gy * HW + gx]) = o;
            }
            if (oc1 < OC) {
                float bz = bias[oc1];
                float2 o = make_float2(cacc[mt][nt][2] + bz, cacc[mt][nt][3] + bz);
                *reinterpret_cast<float2*>(&y[((size_t)(b * OC + oc1)) * HWSZ + gy * HW + gx]) = o;
            }
        }
    }
}

// ---------------- modulated deformable conv: software-pipelined, 1 barrier/tap ----------------
// smem: weights 3 bufs (triple), s_col 2 bufs, s_wgt/s_idx 2 bufs.
// region it: [A(it+1)] bar [prefetch(it+2); gather(it+1); mma(it)]
#define COL_S 136
#define COLB  (32 * COL_S)                       // 4352
#define DCN_SMEM (24576 * 4)                     // 98304 B

__global__ void __launch_bounds__(256, 2) dcn_mma_kernel(const float* __restrict__ x,
                                                         const float* __restrict__ bias,
                                                         float* __restrict__ y) {
    extern __shared__ float sm[];
    float* s_w    = sm;                          // 3 x 4608 = 13824
    float* s_colb = sm + 13824;                  // 2 x 4352 = 8704
    float* s_wgtb = sm + 22528;                  // 2 x 512
    int*   s_idxb = (int*)(sm + 23552);          // 2 x 512

    const int tid = threadIdx.x;
    const int wid = tid >> 5, lane = tid & 31;
    const int warp_m = wid >> 2, warp_n = wid & 3;
    const int lm = lane >> 2, lk = lane & 3;
    const int b = blockIdx.y;
    const int tile_x = (blockIdx.x % 3) * 32;
    const int tile_y = (blockIdx.x / 3) * 4;

    float cacc[4][4][4];
#pragma unroll
    for (int mt = 0; mt < 4; mt++)
#pragma unroll
        for (int nt = 0; nt < 4; nt++)
#pragma unroll
            for (int i = 0; i < 4; i++) cacc[mt][nt][i] = 0.f;

    int pxidx[4], arow[4];
#pragma unroll
    for (int nt = 0; nt < 4; nt++)
        pxidx[nt] = warp_n * 32 + nt * 8 + lm;
#pragma unroll
    for (int mt = 0; mt < 4; mt++)
        arow[mt] = (warp_m * 64 + mt * 16 + lm) * SW_S;

    const float* cob = g_co + (size_t)b * OC2 * HWSZ;
    const float* xb  = x    + (size_t)b * CIN * HWSZ;

    // ---- phase helpers as lambdas ----
    auto phaseA = [&](int idx) {
        int g = idx / 9, k = idx - g * 9;
        int px = tid >> 1, half = tid & 1;
        int gy = tile_y + (px >> 5), gx = tile_x + (px & 31);
        int c_y = g * 18 + 2 * k;
        const float* basep = cob + gy * HW + gx;
        float offy = basep[(size_t)c_y * HWSZ];
        float offx = basep[(size_t)(c_y + 1) * HWSZ];
        float mraw = basep[(size_t)(72 + g * 9 + k) * HWSZ];
        float m  = 1.f / (1.f + __expf(-mraw));
        float ys = (float)gy + (float)(k / 3 - 1) + offy;
        float xs = (float)gx + (float)(k % 3 - 1) + offx;
        float y0f = floorf(ys), x0f = floorf(xs);
        float fy = ys - y0f, fx = xs - x0f;
        int y0 = (int)y0f, x0 = (int)x0f;
        float* wgt = s_wgtb + (idx & 1) * 512;
        int*   idxp = s_idxb + (idx & 1) * 512;
#pragma unroll
        for (int cc = 0; cc < 2; cc++) {
            int cnr = 2 * half + cc;
            int dy = cnr >> 1, dx = cnr & 1;
            int yi = y0 + dy, xi = x0 + dx;
            bool valid = (yi >= 0) && (yi < HW) && (xi >= 0) && (xi < HW);
            float wy = dy ? fy : (1.f - fy);
            float wx = dx ? fx : (1.f - fx);
            int yc = min(max(yi, 0), HW - 1);
            int xc = min(max(xi, 0), HW - 1);
            idxp[px * 4 + cnr] = yc * HW + xc;
            wgt[px * 4 + cnr] = valid ? (wy * wx * m) : 0.f;
        }
    };

    auto gather = [&](int idx) {
        int g = idx / 9;
        const float4* wg4 = reinterpret_cast<const float4*>(s_wgtb + (idx & 1) * 512);
        const int4*   ix4 = reinterpret_cast<const int4*>(s_idxb + (idx & 1) * 512);
        float* col = s_colb + (idx & 1) * COLB;
        const float* xg = xb + (size_t)(g * 32) * HWSZ;
#pragma unroll
        for (int j = 0; j < 16; j++) {
            int e = tid + j * 256;
            int ic = e >> 7, px = e & 127;
            float4 wv = wg4[px];
            int4   iv = ix4[px];
            const float* xp = xg + (size_t)ic * HWSZ;
            float v = wv.x * __ldg(xp + iv.x) + wv.y * __ldg(xp + iv.y)
                    + wv.z * __ldg(xp + iv.z) + wv.w * __ldg(xp + iv.w);
            col[ic * COL_S + px] = to_tf32(v);
        }
    };

    auto do_mma = [&](int it, int wslot) {
        const float* swc = s_w + wslot * WCH;
        const float* col = s_colb + (it & 1) * COLB;
#pragma unroll
        for (int s = 0; s < 4; s++) {
            uint32_t A[4][4], B[4][2];
#pragma unroll
            for (int mt = 0; mt < 4; mt++) {
                const float* ap = swc + arow[mt] + s * 8 + lk * 2;
                float2 f0 = *reinterpret_cast<const float2*>(ap);
                float2 f1 = *reinterpret_cast<const float2*>(ap + 8 * SW_S);
                A[mt][0] = fbits(f0.x); A[mt][2] = fbits(f0.y);
                A[mt][1] = fbits(f1.x); A[mt][3] = fbits(f1.y);
            }
#pragma unroll
            for (int nt = 0; nt < 4; nt++) {
                const float* bp = col + (s * 8 + lk) * COL_S + pxidx[nt];
                B[nt][0] = fbits(bp[0]);
                B[nt][1] = fbits(bp[4 * COL_S]);
            }
#pragma unroll
            for (int mt = 0; mt < 4; mt++)
#pragma unroll
                for (int nt = 0; nt < 4; nt++)
                    mma8(cacc[mt][nt], A[mt], B[nt]);
        }
    };

    // ---- prologue ----
    prefetch_chunk(s_w + 0 * WCH, g_wd2 + 0 * 4096, tid);
    prefetch_chunk(s_w + 1 * WCH, g_wd2 + (size_t)1 * 4096, tid);
    phaseA(0);
    __syncthreads();
    gather(0);

    // ---- main pipeline: 1 barrier per tap ----
    int wslot = 0;   // it % 3
    int pslot = 2;   // (it+2) % 3
    for (int it = 0; it < 36; it++) {
        if (it < 35) phaseA(it + 1);
        __syncthreads();
        if (it < 34) prefetch_chunk(s_w + pslot * WCH, g_wd2 + (size_t)(it + 2) * 4096, tid);
        if (it < 35) gather(it + 1);
        do_mma(it, wslot);
        wslot = (wslot == 2) ? 0 : wslot + 1;
        pslot = (pslot == 2) ? 0 : pslot + 1;
    }

    // epilogue
#pragma unroll
    for (int mt = 0; mt < 4; mt++) {
        int oc0 = warp_m * 64 + mt * 16 + lm;
        int oc1 = oc0 + 8;
        float bz0 = bias[oc0], bz1 = bias[oc1];
#pragma unroll
        for (int nt = 0; nt < 4; nt++) {
            int px0 = warp_n * 32 + nt * 8 + lk * 2;
            int gy = tile_y + (px0 >> 5), gx = tile_x + (px0 & 31);
            *reinterpret_cast<float2*>(&y[((size_t)(b * OC1 + oc0)) * HWSZ + gy * HW + gx]) =
                make_float2(cacc[mt][nt][0] + bz0, cacc[mt][nt][1] + bz0);
            *reinterpret_cast<float2*>(&y[((size_t)(b * OC1 + oc1)) * HWSZ + gy * HW + gx]) =
                make_float2(cacc[mt][nt][2] + bz1, cacc[mt][nt][3] + bz1);
        }
    }
}

// ---------------- launch ----------------
extern "C" void kernel_launch(void* const* d_in, const int* in_sizes, int n_in,
                              void* d_out, int out_size) {
    (void)in_sizes; (void)n_in; (void)out_size;
    const float* x_vq  = (const float*)d_in[0];
    const float* w_off = (const float*)d_in[1];
    const float* b_off = (const float*)d_in[2];
    const float* w_co  = (const float*)d_in[3];
    const float* b_co  = (const float*)d_in[4];
    const float* w_dcn = (const float*)d_in[5];
    const float* b_dcn = (const float*)d_in[6];
    float* out = (float*)d_out;

    cudaFuncSetAttribute(conv_mma_kernel<OC1, 0>, cudaFuncAttributeMaxDynamicSharedMemorySize, CONV_SMEM);
    cudaFuncSetAttribute(conv_mma_kernel<OC2, 1>, cudaFuncAttributeMaxDynamicSharedMemorySize, CONV_SMEM);
    cudaFuncSetAttribute(dcn_mma_kernel, cudaFuncAttributeMaxDynamicSharedMemorySize, DCN_SMEM);

    prep_wA_kernel<<<(36 * 128 * 32 + 255) / 256, 256>>>(w_off, OC1, 0);
    prep_wA_kernel<<<(36 * 128 * 32 + 255) / 256, 256>>>(w_co,  OC2, 1);
    prep_wd_kernel<<<(36 * 128 * 32 + 255) / 256, 256>>>(w_dcn);

    dim3 cgrid(72, BATCH);   // 3x24 tiles of 32x4 px, 128 oc per CTA
    conv_mma_kernel<OC1, 0><<<cgrid, 256, CONV_SMEM>>>(x_vq, b_off);
    conv_mma_kernel<OC2, 1><<<cgrid, 256, CONV_SMEM>>>(nullptr, b_co);

    dim3 dgrid(72, BATCH);   // 3x24 tiles of 32x4 px
    dcn_mma_kernel<<<dgrid, 256, DCN_SMEM>>>(x_vq, b_dcn, out);
}

// round 10
// speedup vs baseline: 2.3078x; 1.0654x over previous
#include <cuda_runtime.h>
#include <cstdint>

#define CIN   128
#define HW    96
#define HWSZ  9216
#define BATCH 4
#define OC1   128
#define OC2   108
#define NDG   4

// ---------------- scratch (static device globals; no allocs) ----------------
__device__ float g_xres[BATCH * OC1 * HWSZ];     // conv1 output
__device__ float g_co  [BATCH * OC2 * HWSZ];     // conv2 output
__device__ float g_wA1 [36 * 128 * 32];          // conv1 W, pair-swizzled (see prep)
__device__ float g_wA2 [36 * 128 * 32];          // conv2 W (oc>=108 zero)
__device__ float g_wd2 [36 * 128 * 32];          // dcn  W [g*9+k][oc][j(perm icl)], tf32

// ---------------- helpers ----------------
__device__ __forceinline__ uint32_t tf32_bits(float x) {
    uint32_t r; asm("cvt.rna.tf32.f32 %0, %1;" : "=r"(r) : "f"(x)); return r;
}
__device__ __forceinline__ float to_tf32(float x) {
    return __uint_as_float(tf32_bits(x));
}
__device__ __forceinline__ void mma8(float c[4], const uint32_t a[4], const uint32_t b[2]) {
    asm volatile("mma.sync.aligned.m16n8k8.row.col.f32.tf32.tf32.f32 "
        "{%0,%1,%2,%3}, {%4,%5,%6,%7}, {%8,%9}, {%0,%1,%2,%3};"
        : "+f"(c[0]), "+f"(c[1]), "+f"(c[2]), "+f"(c[3])
        : "r"(a[0]), "r"(a[1]), "r"(a[2]), "r"(a[3]), "r"(b[0]), "r"(b[1]));
}
__device__ __forceinline__ uint32_t fbits(float x) { return __float_as_uint(x); }

// DCN icl permutation: j = s*8 + lk*2 + e -> icl = s*8 + lk + 4*e
__device__ __forceinline__ int perm_icl(int j) {
    return (j & ~7) + ((j & 7) >> 1) + 4 * (j & 1);
}

#define SW_S   36
#define WCH_C  4096      // conv chunk floats in smem (unpadded, swizzled)
#define WCH_D  4608      // dcn chunk floats in smem (padded stride 36)

// plain float4 copy (conv: global already swizzled)
__device__ __forceinline__ void prefetch_chunk_raw(float* dst, const float* src, int tid) {
#pragma unroll
    for (int j = 0; j < 4; j++) {
        int t4 = tid + j * 256;
        reinterpret_cast<float4*>(dst)[t4] = reinterpret_cast<const float4*>(src)[t4];
    }
}
// padded copy for DCN ([oc][36])
__device__ __forceinline__ void prefetch_chunk_pad(float* dstb, const float* src, int tid) {
#pragma unroll
    for (int j = 0; j < 4; j++) {
        int t4 = tid + j * 256;
        float4 v = reinterpret_cast<const float4*>(src)[t4];
        *reinterpret_cast<float4*>(dstb + (t4 >> 3) * SW_S + (t4 & 7) * 4) = v;
    }
}

// ---------------- weight prep ----------------
// conv: chunk c = icc*9+k. Row oc = 16 float2 pairs; pair p=(s*4+lk) holds
// (icl=s*8+lk, icl+4) and is stored at slot (p + 4*oc) & 15  -> A-frag LDS.64
// hits slot (s*4+lk+4*lm)&15 = 16 slots x 2 lanes (2-phase optimal).
__global__ void prep_wA_kernel(const float* __restrict__ w, int OC, int which) {
    float* dst = which ? g_wA2 : g_wA1;
    int i = blockIdx.x * 256 + threadIdx.x;
    if (i >= 36 * 128 * 32) return;
    int j = i & 31, oc = (i >> 5) & 127, chunk = i >> 12;
    int icc = chunk / 9, k = chunk % 9;
    int slot = j >> 1, e = j & 1;
    int p = (slot - 4 * oc) & 15;
    int icl = (p >> 2) * 8 + (p & 3) + 4 * e;
    int ic = icc * 32 + icl;
    float v = (oc < OC) ? w[(oc * CIN + ic) * 9 + k] : 0.f;
    dst[i] = to_tf32(v);
}
// dcn (permuted for float2 A loads): dst[((g*9+k)*128 + oc)*32 + j]
__global__ void prep_wd_kernel(const float* __restrict__ w) {
    int i = blockIdx.x * 256 + threadIdx.x;
    if (i >= 36 * 128 * 32) return;
    int j = i & 31, oc = (i >> 5) & 127, chunk = i >> 12;
    int g = chunk / 9, k = chunk % 9;
    g_wd2[i] = to_tf32(w[(oc * CIN + g * 32 + perm_icl(j)) * 9 + k]);
}

// ---------------- tf32 mma conv3x3 ----------------
// CTA: 256 thr = 8 warps (2 M x 4 N). Tile M=128 oc, N=128 px (32x4 spatial).
// A via swizzled LDS.64 pairs, B via K-paired float2. 48 LDS / 64 MMA per tap.
#define PAIR_S 216
#define CONV_SMEM ((16*PAIR_S*2 + 4*WCH_C) * 4)   // 27648 + 65536 = 93184 B

__device__ __forceinline__ void conv_tap(float cacc[4][4][4], const float2* stg2,
                                         const float2* swc2, int koff,
                                         const int pxbase[4], const int rowb[4],
                                         int lm, int lk) {
#pragma unroll
    for (int s = 0; s < 4; s++) {
        uint32_t A[4][4], B[4][2];
        const int slot = (s * 4 + lk + 4 * lm) & 15;
#pragma unroll
        for (int mt = 0; mt < 4; mt++) {
            float2 f0 = swc2[rowb[mt] * 16 + slot];
            float2 f1 = swc2[(rowb[mt] + 8) * 16 + slot];
            A[mt][0] = fbits(f0.x); A[mt][2] = fbits(f0.y);
            A[mt][1] = fbits(f1.x); A[mt][3] = fbits(f1.y);
        }
#pragma unroll
        for (int nt = 0; nt < 4; nt++) {
            float2 f = stg2[(s * 4 + lk) * PAIR_S + pxbase[nt] + koff];
            B[nt][0] = fbits(f.x);
            B[nt][1] = fbits(f.y);
        }
#pragma unroll
        for (int mt = 0; mt < 4; mt++)
#pragma unroll
            for (int nt = 0; nt < 4; nt++)
                mma8(cacc[mt][nt], A[mt], B[nt]);
    }
}

template<int OC, int MODE>
__global__ void __launch_bounds__(256, 2) conv_mma_kernel(const float* __restrict__ xin,
                                                          const float* __restrict__ bias) {
    extern __shared__ float sm[];
    float2* stg2 = (float2*)sm;              // [16][216]
    float* swb = sm + 16 * PAIR_S * 2;       // 4 x 4096

    const float* x  = (MODE == 0) ? xin : g_xres;
    const float* wA = (MODE == 0) ? g_wA1 : g_wA2;
    float*       y  = (MODE == 0) ? g_xres : g_co;

    const int tid = threadIdx.x;
    const int wid = tid >> 5, lane = tid & 31;
    const int warp_m = wid >> 2, warp_n = wid & 3;
    const int lm = lane >> 2, lk = lane & 3;
    const int b = blockIdx.y;
    const int tile_x = (blockIdx.x % 3) * 32;
    const int tile_y = (blockIdx.x / 3) * 4;

    float cacc[4][4][4];
#pragma unroll
    for (int mt = 0; mt < 4; mt++)
#pragma unroll
        for (int nt = 0; nt < 4; nt++)
#pragma unroll
            for (int i = 0; i < 4; i++) cacc[mt][nt][i] = 0.f;

    int pxbase[4], rowb[4];
#pragma unroll
    for (int nt = 0; nt < 4; nt++) {
        int px = warp_n * 32 + nt * 8 + lm;
        pxbase[nt] = (px >> 5) * 34 + (px & 31);
    }
#pragma unroll
    for (int mt = 0; mt < 4; mt++)
        rowb[mt] = warp_m * 64 + mt * 16 + lm;

    const float* xb = x + (size_t)b * CIN * HWSZ;

    // preload chunks 0,1
    prefetch_chunk_raw(swb + 0 * WCH_C, wA, tid);
    prefetch_chunk_raw(swb + 1 * WCH_C, wA + 4096, tid);

    int np = 2, c = 0;
    for (int icc = 0; icc < 4; icc++) {
        // stage input chunk as k-paired float2
        for (int i = tid; i < 16 * 204; i += 256) {
            int p = i / 204, rem = i % 204;
            int r = rem / 34, cc2 = rem % 34;
            int s = p >> 2, plk = p & 3;
            int ic1 = icc * 32 + s * 8 + plk;
            int gy = tile_y + r - 1, gx = tile_x + cc2 - 1;
            float v1 = 0.f, v2 = 0.f;
            if (gy >= 0 && gy < HW && gx >= 0 && gx < HW) {
                const float* px0 = xb + (size_t)ic1 * HWSZ + gy * HW + gx;
                v1 = px0[0];
                v2 = px0[4 * HWSZ];
            }
            stg2[p * PAIR_S + rem] = make_float2(to_tf32(v1), to_tf32(v2));
        }
        __syncthreads();

        for (int k0 = 0; k0 < 9; k0 += 2) {
#pragma unroll
            for (int t = 0; t < 2; t++) {
                if (np <= c + 3 && np < 36) {
                    prefetch_chunk_raw(swb + (np & 3) * WCH_C, wA + (size_t)np * 4096, tid);
                    np++;
                }
            }
            {
                const int k = k0;
                conv_tap(cacc, stg2, (const float2*)(swb + (c & 3) * WCH_C),
                         (k / 3) * 34 + (k % 3), pxbase, rowb, lm, lk);
            }
            if (k0 < 8) {
                const int k = k0 + 1;
                conv_tap(cacc, stg2, (const float2*)(swb + ((c + 1) & 3) * WCH_C),
                         (k / 3) * 34 + (k % 3), pxbase, rowb, lm, lk);
                c += 2;
            } else {
                c += 1;
            }
            __syncthreads();
        }
    }

    // epilogue
#pragma unroll
    for (int mt = 0; mt < 4; mt++) {
        int oc0 = warp_m * 64 + mt * 16 + lm;
        int oc1 = oc0 + 8;
#pragma unroll
        for (int nt = 0; nt < 4; nt++) {
            int px0 = warp_n * 32 + nt * 8 + lk * 2;
            int gy = tile_y + (px0 >> 5), gx = tile_x + (px0 & 31);
            if (oc0 < OC) {
                float bz = bias[oc0];
                float2 o = make_float2(cacc[mt][nt][0] + bz, cacc[mt][nt][1] + bz);
                *reinterpret_cast<float2*>(&y[((size_t)(b * OC + oc0)) * HWSZ + gy * HW + gx]) = o;
            }
            if (oc1 < OC) {
                float bz = bias[oc1];
                float2 o = make_float2(cacc[mt][nt][2] + bz, cacc[mt][nt][3] + bz);
                *reinterpret_cast<float2*>(&y[((size_t)(b * OC + oc1)) * HWSZ + gy * HW + gx]) = o;
            }
        }
    }
}

// ---------------- modulated deformable conv: pipelined, gather/MMA interleaved ----------------
// Per tap, 4 quarters: issue 16 LDG -> one k8 MMA s-step (hides LDG latency) -> combine+STS.
#define COL_S 136
#define COLB  (32 * COL_S)                       // 4352
#define DCN_SMEM (24576 * 4)                     // 98304 B

__global__ void __launch_bounds__(256, 2) dcn_mma_kernel(const float* __restrict__ x,
                                                         const float* __restrict__ bias,
                                                         float* __restrict__ y) {
    extern __shared__ float sm[];
    float* s_w    = sm;                          // 3 x 4608 = 13824
    float* s_colb = sm + 13824;                  // 2 x 4352 = 8704
    float* s_wgtb = sm + 22528;                  // 2 x 512
    int*   s_idxb = (int*)(sm + 23552);          // 2 x 512

    const int tid = threadIdx.x;
    const int wid = tid >> 5, lane = tid & 31;
    const int warp_m = wid >> 2, warp_n = wid & 3;
    const int lm = lane >> 2, lk = lane & 3;
    const int b = blockIdx.y;
    const int tile_x = (blockIdx.x % 3) * 32;
    const int tile_y = (blockIdx.x / 3) * 4;

    float cacc[4][4][4];
#pragma unroll
    for (int mt = 0; mt < 4; mt++)
#pragma unroll
        for (int nt = 0; nt < 4; nt++)
#pragma unroll
            for (int i = 0; i < 4; i++) cacc[mt][nt][i] = 0.f;

    int pxidx[4], arow[4];
#pragma unroll
    for (int nt = 0; nt < 4; nt++)
        pxidx[nt] = warp_n * 32 + nt * 8 + lm;
#pragma unroll
    for (int mt = 0; mt < 4; mt++)
        arow[mt] = (warp_m * 64 + mt * 16 + lm) * SW_S;

    const float* cob = g_co + (size_t)b * OC2 * HWSZ;
    const float* xb  = x    + (size_t)b * CIN * HWSZ;

    auto phaseA = [&](int idx) {
        int g = idx / 9, k = idx - g * 9;
        int px = tid >> 1, half = tid & 1;
        int gy = tile_y + (px >> 5), gx = tile_x + (px & 31);
        int c_y = g * 18 + 2 * k;
        const float* basep = cob + gy * HW + gx;
        float offy = basep[(size_t)c_y * HWSZ];
        float offx = basep[(size_t)(c_y + 1) * HWSZ];
        float mraw = basep[(size_t)(72 + g * 9 + k) * HWSZ];
        float m  = 1.f / (1.f + __expf(-mraw));
        float ys = (float)gy + (float)(k / 3 - 1) + offy;
        float xs = (float)gx + (float)(k % 3 - 1) + offx;
        float y0f = floorf(ys), x0f = floorf(xs);
        float fy = ys - y0f, fx = xs - x0f;
        int y0 = (int)y0f, x0 = (int)x0f;
        float* wgt = s_wgtb + (idx & 1) * 512;
        int*   idxp = s_idxb + (idx & 1) * 512;
#pragma unroll
        for (int cc = 0; cc < 2; cc++) {
            int cnr = 2 * half + cc;
            int dy = cnr >> 1, dx = cnr & 1;
            int yi = y0 + dy, xi = x0 + dx;
            bool valid = (yi >= 0) && (yi < HW) && (xi >= 0) && (xi < HW);
            float wy = dy ? fy : (1.f - fy);
            float wx = dx ? fx : (1.f - fx);
            int yc = min(max(yi, 0), HW - 1);
            int xc = min(max(xi, 0), HW - 1);
            idxp[px * 4 + cnr] = yc * HW + xc;
            wgt[px * 4 + cnr] = valid ? (wy * wx * m) : 0.f;
        }
    };

    // issue 16 LDGs for quarter q of tap idx (4 elements x 4 corners)
    auto issue_loads = [&](int idx, int q, float vals[16]) {
        int g = idx / 9;
        const int4* ix4 = reinterpret_cast<const int4*>(s_idxb + (idx & 1) * 512);
        const float* xg = xb + (size_t)(g * 32) * HWSZ;
#pragma unroll
        for (int jj = 0; jj < 4; jj++) {
            int e = tid + (q * 4 + jj) * 256;
            int ic = e >> 7, px = e & 127;
            int4 iv = ix4[px];
            const float* xp = xg + (size_t)ic * HWSZ;
            vals[jj * 4 + 0] = __ldg(xp + iv.x);
            vals[jj * 4 + 1] = __ldg(xp + iv.y);
            vals[jj * 4 + 2] = __ldg(xp + iv.z);
            vals[jj * 4 + 3] = __ldg(xp + iv.w);
        }
    };
    auto combine = [&](int idx, int q, const float vals[16]) {
        const float4* wg4 = reinterpret_cast<const float4*>(s_wgtb + (idx & 1) * 512);
        float* col = s_colb + (idx & 1) * COLB;
#pragma unroll
        for (int jj = 0; jj < 4; jj++) {
            int e = tid + (q * 4 + jj) * 256;
            int ic = e >> 7, px = e & 127;
            float4 wv = wg4[px];
            float v = wv.x * vals[jj * 4 + 0] + wv.y * vals[jj * 4 + 1]
                    + wv.z * vals[jj * 4 + 2] + wv.w * vals[jj * 4 + 3];
            col[ic * COL_S + px] = to_tf32(v);
        }
    };

    auto do_mma_s = [&](int it, int wslot, int s) {
        const float* swc = s_w + wslot * WCH_D;
        const float* col = s_colb + (it & 1) * COLB;
        uint32_t A[4][4], B[4][2];
#pragma unroll
        for (int mt = 0; mt < 4; mt++) {
            const float* ap = swc + arow[mt] + s * 8 + lk * 2;
            float2 f0 = *reinterpret_cast<const float2*>(ap);
            float2 f1 = *reinterpret_cast<const float2*>(ap + 8 * SW_S);
            A[mt][0] = fbits(f0.x); A[mt][2] = fbits(f0.y);
            A[mt][1] = fbits(f1.x); A[mt][3] = fbits(f1.y);
        }
#pragma unroll
        for (int nt = 0; nt < 4; nt++) {
            const float* bp = col + (s * 8 + lk) * COL_S + pxidx[nt];
            B[nt][0] = fbits(bp[0]);
            B[nt][1] = fbits(bp[4 * COL_S]);
        }
#pragma unroll
        for (int mt = 0; mt < 4; mt++)
#pragma unroll
            for (int nt = 0; nt < 4; nt++)
                mma8(cacc[mt][nt], A[mt], B[nt]);
    };

    // ---- prologue ----
    prefetch_chunk_pad(s_w + 0 * WCH_D, g_wd2, tid);
    prefetch_chunk_pad(s_w + 1 * WCH_D, g_wd2 + 4096, tid);
    phaseA(0);
    __syncthreads();
    {   // gather tap 0 (no mma to overlap yet)
        float vals[16];
#pragma unroll
        for (int q = 0; q < 4; q++) { issue_loads(0, q, vals); combine(0, q, vals); }
    }

    // ---- main pipeline: 1 barrier per tap, gather/MMA interleaved ----
    int wslot = 0;   // it % 3
    int pslot = 2;   // (it+2) % 3
    for (int it = 0; it < 36; it++) {
        if (it < 35) phaseA(it + 1);
        __syncthreads();
        if (it < 34) prefetch_chunk_pad(s_w + pslot * WCH_D, g_wd2 + (size_t)(it + 2) * 4096, tid);
        if (it < 35) {
            float vals[16];
#pragma unroll
            for (int q = 0; q < 4; q++) {
                issue_loads(it + 1, q, vals);
                do_mma_s(it, wslot, q);
                combine(it + 1, q, vals);
            }
        } else {
#pragma unroll
            for (int q = 0; q < 4; q++) do_mma_s(it, wslot, q);
        }
        wslot = (wslot == 2) ? 0 : wslot + 1;
        pslot = (pslot == 2) ? 0 : pslot + 1;
    }

    // epilogue
#pragma unroll
    for (int mt = 0; mt < 4; mt++) {
        int oc0 = warp_m * 64 + mt * 16 + lm;
        int oc1 = oc0 + 8;
        float bz0 = bias[oc0], bz1 = bias[oc1];
#pragma unroll
        for (int nt = 0; nt < 4; nt++) {
            int px0 = warp_n * 32 + nt * 8 + lk * 2;
            int gy = tile_y + (px0 >> 5), gx = tile_x + (px0 & 31);
            *reinterpret_cast<float2*>(&y[((size_t)(b * OC1 + oc0)) * HWSZ + gy * HW + gx]) =
                make_float2(cacc[mt][nt][0] + bz0, cacc[mt][nt][1] + bz0);
            *reinterpret_cast<float2*>(&y[((size_t)(b * OC1 + oc1)) * HWSZ + gy * HW + gx]) =
                make_float2(cacc[mt][nt][2] + bz1, cacc[mt][nt][3] + bz1);
        }
    }
}

// ---------------- launch ----------------
extern "C" void kernel_launch(void* const* d_in, const int* in_sizes, int n_in,
                              void* d_out, int out_size) {
    (void)in_sizes; (void)n_in; (void)out_size;
    const float* x_vq  = (const float*)d_in[0];
    const float* w_off = (const float*)d_in[1];
    const float* b_off = (const float*)d_in[2];
    const float* w_co  = (const float*)d_in[3];
    const float* b_co  = (const float*)d_in[4];
    const float* w_dcn = (const float*)d_in[5];
    const float* b_dcn = (const float*)d_in[6];
    float* out = (float*)d_out;

    cudaFuncSetAttribute(conv_mma_kernel<OC1, 0>, cudaFuncAttributeMaxDynamicSharedMemorySize, CONV_SMEM);
    cudaFuncSetAttribute(conv_mma_kernel<OC2, 1>, cudaFuncAttributeMaxDynamicSharedMemorySize, CONV_SMEM);
    cudaFuncSetAttribute(dcn_mma_kernel, cudaFuncAttributeMaxDynamicSharedMemorySize, DCN_SMEM);

    prep_wA_kernel<<<(36 * 128 * 32 + 255) / 256, 256>>>(w_off, OC1, 0);
    prep_wA_kernel<<<(36 * 128 * 32 + 255) / 256, 256>>>(w_co,  OC2, 1);
    prep_wd_kernel<<<(36 * 128 * 32 + 255) / 256, 256>>>(w_dcn);

    dim3 cgrid(72, BATCH);   // 3x24 tiles of 32x4 px, 128 oc per CTA
    conv_mma_kernel<OC1, 0><<<cgrid, 256, CONV_SMEM>>>(x_vq, b_off);
    conv_mma_kernel<OC2, 1><<<cgrid, 256, CONV_SMEM>>>(nullptr, b_co);

    dim3 dgrid(72, BATCH);   // 3x24 tiles of 32x4 px
    dcn_mma_kernel<<<dgrid, 256, DCN_SMEM>>>(x_vq, b_dcn, out);
}

// round 11
// speedup vs baseline: 2.7931x; 1.2103x over previous
#include <cuda_runtime.h>
#include <cstdint>

#define CIN   128
#define HW    96
#define HWSZ  9216
#define BATCH 4
#define OC1   128
#define OC2   108
#define NDG   4

// ---------------- scratch (static device globals; no allocs) ----------------
__device__ float g_xres[BATCH * OC1 * HWSZ];     // conv1 output
__device__ float g_co  [BATCH * OC2 * HWSZ];     // conv2 output
__device__ float g_wA1 [36 * 128 * 32];          // conv1 W, pair-swizzled (see prep)
__device__ float g_wA2 [36 * 128 * 32];          // conv2 W (oc>=108 zero)
__device__ float g_wd2 [36 * 128 * 32];          // dcn  W [g*9+k][oc][j(perm icl)], tf32

// ---------------- helpers ----------------
__device__ __forceinline__ uint32_t tf32_bits(float x) {
    uint32_t r; asm("cvt.rna.tf32.f32 %0, %1;" : "=r"(r) : "f"(x)); return r;
}
__device__ __forceinline__ float to_tf32(float x) {
    return __uint_as_float(tf32_bits(x));
}
__device__ __forceinline__ void mma8(float c[4], const uint32_t a[4], const uint32_t b[2]) {
    asm volatile("mma.sync.aligned.m16n8k8.row.col.f32.tf32.tf32.f32 "
        "{%0,%1,%2,%3}, {%4,%5,%6,%7}, {%8,%9}, {%0,%1,%2,%3};"
        : "+f"(c[0]), "+f"(c[1]), "+f"(c[2]), "+f"(c[3])
        : "r"(a[0]), "r"(a[1]), "r"(a[2]), "r"(a[3]), "r"(b[0]), "r"(b[1]));
}
__device__ __forceinline__ uint32_t fbits(float x) { return __float_as_uint(x); }

__device__ __forceinline__ uint32_t smem_u32(const void* p) {
    return (uint32_t)__cvta_generic_to_shared(p);
}
__device__ __forceinline__ void cp_async16(uint32_t saddr, const void* g) {
    asm volatile("cp.async.cg.shared.global [%0], [%1], 16;" :: "r"(saddr), "l"(g));
}
#define CP_WAIT_ALL() asm volatile("cp.async.wait_all;" ::: "memory")

// DCN icl permutation: j = s*8 + lk*2 + e -> icl = s*8 + lk + 4*e
__device__ __forceinline__ int perm_icl(int j) {
    return (j & ~7) + ((j & 7) >> 1) + 4 * (j & 1);
}

#define SW_S   36
#define WCH_C  4096      // conv chunk floats in smem (unpadded, swizzled)
#define WCH_D  4608      // dcn chunk floats in smem (padded stride 36)

// async weight prefetches (cp.async; completion via CP_WAIT_ALL before barrier)
__device__ __forceinline__ void prefetch_raw_cp(float* dst, const float* src, int tid) {
    uint32_t base = smem_u32(dst);
#pragma unroll
    for (int j = 0; j < 4; j++) {
        int t4 = tid + j * 256;
        cp_async16(base + t4 * 16, src + t4 * 4);
    }
}
__device__ __forceinline__ void prefetch_pad_cp(float* dstb, const float* src, int tid) {
    uint32_t base = smem_u32(dstb);
#pragma unroll
    for (int j = 0; j < 4; j++) {
        int t4 = tid + j * 256;
        uint32_t off = (uint32_t)((t4 >> 3) * SW_S + (t4 & 7) * 4) * 4;   // 16B-aligned
        cp_async16(base + off, src + t4 * 4);
    }
}

// ---------------- weight prep ----------------
// conv: chunk c = icc*9+k. Row oc = 16 float2 pairs; pair p=(s*4+lk) at slot
// (p + 4*oc) & 15 -> A-frag LDS.64 hits 16 slots x 2 lanes (2-phase optimal).
__global__ void prep_wA_kernel(const float* __restrict__ w, int OC, int which) {
    float* dst = which ? g_wA2 : g_wA1;
    int i = blockIdx.x * 256 + threadIdx.x;
    if (i >= 36 * 128 * 32) return;
    int j = i & 31, oc = (i >> 5) & 127, chunk = i >> 12;
    int icc = chunk / 9, k = chunk % 9;
    int slot = j >> 1, e = j & 1;
    int p = (slot - 4 * oc) & 15;
    int icl = (p >> 2) * 8 + (p & 3) + 4 * e;
    int ic = icc * 32 + icl;
    float v = (oc < OC) ? w[(oc * CIN + ic) * 9 + k] : 0.f;
    dst[i] = to_tf32(v);
}
// dcn (permuted for float2 A loads): dst[((g*9+k)*128 + oc)*32 + j]
__global__ void prep_wd_kernel(const float* __restrict__ w) {
    int i = blockIdx.x * 256 + threadIdx.x;
    if (i >= 36 * 128 * 32) return;
    int j = i & 31, oc = (i >> 5) & 127, chunk = i >> 12;
    int g = chunk / 9, k = chunk % 9;
    g_wd2[i] = to_tf32(w[(oc * CIN + g * 32 + perm_icl(j)) * 9 + k]);
}

// ---------------- tf32 mma conv3x3 ----------------
#define PAIR_S 216
#define CONV_SMEM ((16*PAIR_S*2 + 4*WCH_C) * 4)   // 27648 + 65536 = 93184 B

__device__ __forceinline__ void conv_tap(float cacc[4][4][4], const float2* stg2,
                                         const float2* swc2, int koff,
                                         const int pxbase[4], const int rowb[4],
                                         int lm, int lk) {
#pragma unroll
    for (int s = 0; s < 4; s++) {
        uint32_t A[4][4], B[4][2];
        const int slot = (s * 4 + lk + 4 * lm) & 15;
#pragma unroll
        for (int mt = 0; mt < 4; mt++) {
            float2 f0 = swc2[rowb[mt] * 16 + slot];
            float2 f1 = swc2[(rowb[mt] + 8) * 16 + slot];
            A[mt][0] = fbits(f0.x); A[mt][2] = fbits(f0.y);
            A[mt][1] = fbits(f1.x); A[mt][3] = fbits(f1.y);
        }
#pragma unroll
        for (int nt = 0; nt < 4; nt++) {
            float2 f = stg2[(s * 4 + lk) * PAIR_S + pxbase[nt] + koff];
            B[nt][0] = fbits(f.x);
            B[nt][1] = fbits(f.y);
        }
#pragma unroll
        for (int mt = 0; mt < 4; mt++)
#pragma unroll
            for (int nt = 0; nt < 4; nt++)
                mma8(cacc[mt][nt], A[mt], B[nt]);
    }
}

template<int OC, int MODE>
__global__ void __launch_bounds__(256, 2) conv_mma_kernel(const float* __restrict__ xin,
                                                          const float* __restrict__ bias) {
    extern __shared__ float sm[];
    float2* stg2 = (float2*)sm;              // [16][216]
    float* swb = sm + 16 * PAIR_S * 2;       // 4 x 4096

    const float* x  = (MODE == 0) ? xin : g_xres;
    const float* wA = (MODE == 0) ? g_wA1 : g_wA2;
    float*       y  = (MODE == 0) ? g_xres : g_co;

    const int tid = threadIdx.x;
    const int wid = tid >> 5, lane = tid & 31;
    const int warp_m = wid >> 2, warp_n = wid & 3;
    const int lm = lane >> 2, lk = lane & 3;
    const int b = blockIdx.y;
    const int tile_x = (blockIdx.x % 3) * 32;
    const int tile_y = (blockIdx.x / 3) * 4;

    float cacc[4][4][4];
#pragma unroll
    for (int mt = 0; mt < 4; mt++)
#pragma unroll
        for (int nt = 0; nt < 4; nt++)
#pragma unroll
            for (int i = 0; i < 4; i++) cacc[mt][nt][i] = 0.f;

    int pxbase[4], rowb[4];
#pragma unroll
    for (int nt = 0; nt < 4; nt++) {
        int px = warp_n * 32 + nt * 8 + lm;
        pxbase[nt] = (px >> 5) * 34 + (px & 31);
    }
#pragma unroll
    for (int mt = 0; mt < 4; mt++)
        rowb[mt] = warp_m * 64 + mt * 16 + lm;

    const float* xb = x + (size_t)b * CIN * HWSZ;

    // preload chunks 0,1 (async)
    prefetch_raw_cp(swb + 0 * WCH_C, wA, tid);
    prefetch_raw_cp(swb + 1 * WCH_C, wA + 4096, tid);

    int np = 2, c = 0;
    for (int icc = 0; icc < 4; icc++) {
        // stage input chunk as k-paired float2
        for (int i = tid; i < 16 * 204; i += 256) {
            int p = i / 204, rem = i % 204;
            int r = rem / 34, cc2 = rem % 34;
            int s = p >> 2, plk = p & 3;
            int ic1 = icc * 32 + s * 8 + plk;
            int gy = tile_y + r - 1, gx = tile_x + cc2 - 1;
            float v1 = 0.f, v2 = 0.f;
            if (gy >= 0 && gy < HW && gx >= 0 && gx < HW) {
                const float* px0 = xb + (size_t)ic1 * HWSZ + gy * HW + gx;
                v1 = px0[0];
                v2 = px0[4 * HWSZ];
            }
            stg2[p * PAIR_S + rem] = make_float2(to_tf32(v1), to_tf32(v2));
        }
        CP_WAIT_ALL();
        __syncthreads();

        for (int k0 = 0; k0 < 9; k0 += 2) {
#pragma unroll
            for (int t = 0; t < 2; t++) {
                if (np <= c + 3 && np < 36) {
                    prefetch_raw_cp(swb + (np & 3) * WCH_C, wA + (size_t)np * 4096, tid);
                    np++;
                }
            }
            {
                const int k = k0;
                conv_tap(cacc, stg2, (const float2*)(swb + (c & 3) * WCH_C),
                         (k / 3) * 34 + (k % 3), pxbase, rowb, lm, lk);
            }
            if (k0 < 8) {
                const int k = k0 + 1;
                conv_tap(cacc, stg2, (const float2*)(swb + ((c + 1) & 3) * WCH_C),
                         (k / 3) * 34 + (k % 3), pxbase, rowb, lm, lk);
                c += 2;
            } else {
                c += 1;
            }
            CP_WAIT_ALL();
            __syncthreads();
        }
    }

    // epilogue
#pragma unroll
    for (int mt = 0; mt < 4; mt++) {
        int oc0 = warp_m * 64 + mt * 16 + lm;
        int oc1 = oc0 + 8;
#pragma unroll
        for (int nt = 0; nt < 4; nt++) {
            int px0 = warp_n * 32 + nt * 8 + lk * 2;
            int gy = tile_y + (px0 >> 5), gx = tile_x + (px0 & 31);
            if (oc0 < OC) {
                float bz = bias[oc0];
                float2 o = make_float2(cacc[mt][nt][0] + bz, cacc[mt][nt][1] + bz);
                *reinterpret_cast<float2*>(&y[((size_t)(b * OC + oc0)) * HWSZ + gy * HW + gx]) = o;
            }
            if (oc1 < OC) {
                float bz = bias[oc1];
                float2 o = make_float2(cacc[mt][nt][2] + bz, cacc[mt][nt][3] + bz);
                *reinterpret_cast<float2*>(&y[((size_t)(b * OC + oc1)) * HWSZ + gy * HW + gx]) = o;
            }
        }
    }
}

// ---------------- modulated deformable conv ----------------
// Per-thread bilinear params in REGISTERS (px = tid&127 is constant per thread):
// no s_idx/s_wgt smem, no param STS/LDS. Pipelined: 1 barrier/tap, gather/MMA
// interleaved in quarters, cp.async weight prefetch (triple-buffered).
#define COL_S 136
#define COLB  (32 * COL_S)                       // 4352
#define DCN_SMEM ((3*WCH_D + 2*COLB) * 4)        // 13824 + 8704 floats = 90112 B

__global__ void __launch_bounds__(256, 2) dcn_mma_kernel(const float* __restrict__ x,
                                                         const float* __restrict__ bias,
                                                         float* __restrict__ y) {
    extern __shared__ float sm[];
    float* s_w    = sm;                          // 3 x 4608
    float* s_colb = sm + 3 * WCH_D;              // 2 x 4352

    const int tid = threadIdx.x;
    const int wid = tid >> 5, lane = tid & 31;
    const int warp_m = wid >> 2, warp_n = wid & 3;
    const int lm = lane >> 2, lk = lane & 3;
    const int b = blockIdx.y;
    const int tile_x = (blockIdx.x % 3) * 32;
    const int tile_y = (blockIdx.x / 3) * 4;

    const int px_own = tid & 127;                // gather pixel (constant per thread)
    const int icb    = tid >> 7;                 // 0/1: ic parity base
    const int gy_own = tile_y + (px_own >> 5);
    const int gx_own = tile_x + (px_own & 31);

    float cacc[4][4][4];
#pragma unroll
    for (int mt = 0; mt < 4; mt++)
#pragma unroll
        for (int nt = 0; nt < 4; nt++)
#pragma unroll
            for (int i = 0; i < 4; i++) cacc[mt][nt][i] = 0.f;

    int pxidx[4], arow[4];
#pragma unroll
    for (int nt = 0; nt < 4; nt++)
        pxidx[nt] = warp_n * 32 + nt * 8 + lm;
#pragma unroll
    for (int mt = 0; mt < 4; mt++)
        arow[mt] = (warp_m * 64 + mt * 16 + lm) * SW_S;

    const float* cob = g_co + (size_t)b * OC2 * HWSZ;
    const float* xb  = x    + (size_t)b * CIN * HWSZ;

    // bilinear params for tap idx, all 4 corners, into registers
    auto phaseA_reg = [&](int idx, int4& iv, float4& wv) {
        int g = idx / 9, k = idx - g * 9;
        int c_y = g * 18 + 2 * k;
        const float* basep = cob + gy_own * HW + gx_own;
        float offy = basep[(size_t)c_y * HWSZ];
        float offx = basep[(size_t)(c_y + 1) * HWSZ];
        float mraw = basep[(size_t)(72 + g * 9 + k) * HWSZ];
        float m  = 1.f / (1.f + __expf(-mraw));
        float ys = (float)gy_own + (float)(k / 3 - 1) + offy;
        float xs = (float)gx_own + (float)(k % 3 - 1) + offx;
        float y0f = floorf(ys), x0f = floorf(xs);
        float fy = ys - y0f, fx = xs - x0f;
        int y0 = (int)y0f, x0 = (int)x0f;
        int idxs[4]; float wgts[4];
#pragma unroll
        for (int cnr = 0; cnr < 4; cnr++) {
            int dy = cnr >> 1, dx = cnr & 1;
            int yi = y0 + dy, xi = x0 + dx;
            bool valid = (yi >= 0) && (yi < HW) && (xi >= 0) && (xi < HW);
            float wy = dy ? fy : (1.f - fy);
            float wx = dx ? fx : (1.f - fx);
            int yc = min(max(yi, 0), HW - 1);
            int xc = min(max(xi, 0), HW - 1);
            idxs[cnr] = yc * HW + xc;
            wgts[cnr] = valid ? (wy * wx * m) : 0.f;
        }
        iv = make_int4(idxs[0], idxs[1], idxs[2], idxs[3]);
        wv = make_float4(wgts[0], wgts[1], wgts[2], wgts[3]);
    };

    auto issue_loads = [&](int g, int q, const int4 iv, float vals[16]) {
        const float* xg = xb + (size_t)(g * 32 + icb) * HWSZ;
#pragma unroll
        for (int jj = 0; jj < 4; jj++) {
            const float* xp = xg + (size_t)((q * 4 + jj) * 2) * HWSZ;
            vals[jj * 4 + 0] = __ldg(xp + iv.x);
            vals[jj * 4 + 1] = __ldg(xp + iv.y);
            vals[jj * 4 + 2] = __ldg(xp + iv.z);
            vals[jj * 4 + 3] = __ldg(xp + iv.w);
        }
    };
    auto combine = [&](int it1, int q, const float4 wv, const float vals[16]) {
        float* col = s_colb + (it1 & 1) * COLB;
#pragma unroll
        for (int jj = 0; jj < 4; jj++) {
            int ic = icb + (q * 4 + jj) * 2;
            float v = wv.x * vals[jj * 4 + 0] + wv.y * vals[jj * 4 + 1]
                    + wv.z * vals[jj * 4 + 2] + wv.w * vals[jj * 4 + 3];
            col[ic * COL_S + px_own] = to_tf32(v);
        }
    };

    auto do_mma_s = [&](int it, int wslot, int s) {
        const float* swc = s_w + wslot * WCH_D;
        const float* col = s_colb + (it & 1) * COLB;
        uint32_t A[4][4], B[4][2];
#pragma unroll
        for (int mt = 0; mt < 4; mt++) {
            const float* ap = swc + arow[mt] + s * 8 + lk * 2;
            float2 f0 = *reinterpret_cast<const float2*>(ap);
            float2 f1 = *reinterpret_cast<const float2*>(ap + 8 * SW_S);
            A[mt][0] = fbits(f0.x); A[mt][2] = fbits(f0.y);
            A[mt][1] = fbits(f1.x); A[mt][3] = fbits(f1.y);
        }
#pragma unroll
        for (int nt = 0; nt < 4; nt++) {
            const float* bp = col + (s * 8 + lk) * COL_S + pxidx[nt];
            B[nt][0] = fbits(bp[0]);
            B[nt][1] = fbits(bp[4 * COL_S]);
        }
#pragma unroll
        for (int mt = 0; mt < 4; mt++)
#pragma unroll
            for (int nt = 0; nt < 4; nt++)
                mma8(cacc[mt][nt], A[mt], B[nt]);
    };

    // ---- prologue ----
    prefetch_pad_cp(s_w + 0 * WCH_D, g_wd2, tid);
    prefetch_pad_cp(s_w + 1 * WCH_D, g_wd2 + 4096, tid);
    {
        int4 iv; float4 wv;
        phaseA_reg(0, iv, wv);
        float vals[16];
#pragma unroll
        for (int q = 0; q < 4; q++) { issue_loads(0, q, iv, vals); combine(0, q, wv, vals); }
    }

    // ---- main pipeline: 1 barrier per tap ----
    int wslot = 0;   // it % 3
    int pslot = 2;   // (it+2) % 3
    for (int it = 0; it < 36; it++) {
        int4 ivn; float4 wvn;
        if (it < 35) phaseA_reg(it + 1, ivn, wvn);
        CP_WAIT_ALL();
        __syncthreads();
        if (it < 34) prefetch_pad_cp(s_w + pslot * WCH_D, g_wd2 + (size_t)(it + 2) * 4096, tid);
        if (it < 35) {
            int gn = (it + 1) / 9;
            float vals[16];
#pragma unroll
            for (int q = 0; q < 4; q++) {
                issue_loads(gn, q, ivn, vals);
                do_mma_s(it, wslot, q);
                combine(it + 1, q, wvn, vals);
            }
        } else {
#pragma unroll
            for (int q = 0; q < 4; q++) do_mma_s(it, wslot, q);
        }
        wslot = (wslot == 2) ? 0 : wslot + 1;
        pslot = (pslot == 2) ? 0 : pslot + 1;
    }

    // epilogue
#pragma unroll
    for (int mt = 0; mt < 4; mt++) {
        int oc0 = warp_m * 64 + mt * 16 + lm;
        int oc1 = oc0 + 8;
        float bz0 = bias[oc0], bz1 = bias[oc1];
#pragma unroll
        for (int nt = 0; nt < 4; nt++) {
            int px0 = warp_n * 32 + nt * 8 + lk * 2;
            int gy = tile_y + (px0 >> 5), gx = tile_x + (px0 & 31);
            *reinterpret_cast<float2*>(&y[((size_t)(b * OC1 + oc0)) * HWSZ + gy * HW + gx]) =
                make_float2(cacc[mt][nt][0] + bz0, cacc[mt][nt][1] + bz0);
            *reinterpret_cast<float2*>(&y[((size_t)(b * OC1 + oc1)) * HWSZ + gy * HW + gx]) =
                make_float2(cacc[mt][nt][2] + bz1, cacc[mt][nt][3] + bz1);
        }
    }
}

// ---------------- launch ----------------
extern "C" void kernel_launch(void* const* d_in, const int* in_sizes, int n_in,
                              void* d_out, int out_size) {
    (void)in_sizes; (void)n_in; (void)out_size;
    const float* x_vq  = (const float*)d_in[0];
    const float* w_off = (const float*)d_in[1];
    const float* b_off = (const float*)d_in[2];
    const float* w_co  = (const float*)d_in[3];
    const float* b_co  = (const float*)d_in[4];
    const float* w_dcn = (const float*)d_in[5];
    const float* b_dcn = (const float*)d_in[6];
    float* out = (float*)d_out;

    cudaFuncSetAttribute(conv_mma_kernel<OC1, 0>, cudaFuncAttributeMaxDynamicSharedMemorySize, CONV_SMEM);
    cudaFuncSetAttribute(conv_mma_kernel<OC2, 1>, cudaFuncAttributeMaxDynamicSharedMemorySize, CONV_SMEM);
    cudaFuncSetAttribute(dcn_mma_kernel, cudaFuncAttributeMaxDynamicSharedMemorySize, DCN_SMEM);

    prep_wA_kernel<<<(36 * 128 * 32 + 255) / 256, 256>>>(w_off, OC1, 0);
    prep_wA_kernel<<<(36 * 128 * 32 + 255) / 256, 256>>>(w_co,  OC2, 1);
    prep_wd_kernel<<<(36 * 128 * 32 + 255) / 256, 256>>>(w_dcn);

    dim3 cgrid(72, BATCH);   // 3x24 tiles of 32x4 px, 128 oc per CTA
    conv_mma_kernel<OC1, 0><<<cgrid, 256, CONV_SMEM>>>(x_vq, b_off);
    conv_mma_kernel<OC2, 1><<<cgrid, 256, CONV_SMEM>>>(nullptr, b_co);

    dim3 dgrid(72, BATCH);   // 3x24 tiles of 32x4 px
    dcn_mma_kernel<<<dgrid, 256, DCN_SMEM>>>(x_vq, b_dcn, out);
}

// round 12
// speedup vs baseline: 4.2539x; 1.5230x over previous
#include <cuda_runtime.h>
#include <cuda_fp16.h>
#include <cstdint>

#define CIN   128
#define HW    96
#define HWSZ  9216
#define BATCH 4
#define OC1   128
#define OC2   108
#define NDG   4

// ---------------- scratch (static device globals; no allocs) ----------------
__device__ float    g_xres[BATCH * OC1 * HWSZ];  // conv1 output
__device__ float    g_co  [BATCH * OC2 * HWSZ];  // conv2 output
// fp16 weights, group-packed + rotation-swizzled: [chunk][oc][slot(8)][hl(2)] u32=half2
__device__ uint32_t g_wA1h[36 * 128 * 16];
__device__ uint32_t g_wA2h[36 * 128 * 16];
__device__ uint32_t g_wdh [36 * 128 * 16];

// ---------------- helpers ----------------
__device__ __forceinline__ void mma16(float c[4], const uint32_t a[4], const uint32_t b[2]) {
    asm volatile("mma.sync.aligned.m16n8k16.row.col.f32.f16.f16.f32 "
        "{%0,%1,%2,%3}, {%4,%5,%6,%7}, {%8,%9}, {%0,%1,%2,%3};"
        : "+f"(c[0]), "+f"(c[1]), "+f"(c[2]), "+f"(c[3])
        : "r"(a[0]), "r"(a[1]), "r"(a[2]), "r"(a[3]), "r"(b[0]), "r"(b[1]));
}
__device__ __forceinline__ uint32_t pack_h2(float a, float b) {
    __half2 h = __floats2half2_rn(a, b);
    return *reinterpret_cast<uint32_t*>(&h);
}
__device__ __forceinline__ uint32_t smem_u32(const void* p) {
    return (uint32_t)__cvta_generic_to_shared(p);
}
__device__ __forceinline__ void cp_async16(uint32_t saddr, const void* g) {
    asm volatile("cp.async.cg.shared.global [%0], [%1], 16;" :: "r"(saddr), "l"(g));
}
#define CP_WAIT_ALL() asm volatile("cp.async.wait_all;" ::: "memory")

// async copy of one 8KB weight chunk (2048 u32, flat)
__device__ __forceinline__ void prefetch_w_cp(uint32_t* dst, const uint32_t* src, int tid) {
    uint32_t base = smem_u32(dst);
#pragma unroll
    for (int j = 0; j < 2; j++) {
        int t4 = tid + j * 256;
        cp_async16(base + t4 * 16, src + t4 * 4);
    }
}

// ---------------- weight prep (shared by conv1/conv2/dcn) ----------------
// Group g2 = s*4+lk holds channels {16s+2lk, +1} (hl=0) and {16s+2lk+8, +9} (hl=1)
// of the chunk's 32-channel K-slice. Stored at slot (g2 + oc) & 7 per oc row.
__global__ void prep_wh_kernel(const float* __restrict__ w, int OC, int which) {
    uint32_t* dst = (which == 0) ? g_wA1h : (which == 1) ? g_wA2h : g_wdh;
    int i = blockIdx.x * 256 + threadIdx.x;
    if (i >= 36 * 128 * 16) return;
    int j = i & 15, oc = (i >> 4) & 127, chunk = i >> 11;
    int slot = j >> 1, hl = j & 1;
    int g2 = (slot - oc) & 7;
    int s = g2 >> 2, lkp = g2 & 3;
    int kb = 16 * s + 2 * lkp + 8 * hl;
    int grp = chunk / 9, ktap = chunk % 9;
    int ic0 = grp * 32 + kb;
    float v0 = 0.f, v1 = 0.f;
    if (oc < OC) {
        v0 = w[(oc * CIN + ic0) * 9 + ktap];
        v1 = w[(oc * CIN + ic0 + 1) * 9 + ktap];
    }
    dst[i] = pack_h2(v0, v1);
}

// ---------------- fp16 mma conv3x3 ----------------
// CTA: 256 thr = 8 warps (2M x 4N). Tile M=128 oc, N=128 px (32x4), K=1152 as
// 36 chunks (icc*9+k) of 32, each = 2 m16n8k16 steps. Per tap: 24 LDS.64 + 32 MMA.
#define PAIR_S 216           // uint2 stride (mod 16 = 8 -> 2-phase optimal)
#define CONV_SMEM ((8*PAIR_S*2 + 4*2048) * 4)   // 13824 + 32768 = 46592 B

__device__ __forceinline__ void conv_tap(float cacc[4][4][4], const uint2* stg4,
                                         const uint2* swc4, int koff,
                                         const int pxbase[4], const int rowb[4], int lk) {
#pragma unroll
    for (int s = 0; s < 2; s++) {
        uint32_t A[4][4], B4[4][2];
#pragma unroll
        for (int mt = 0; mt < 4; mt++) {
            int r0 = rowb[mt];
            uint2 u = swc4[r0 * 8 + ((s * 4 + lk + r0) & 7)];
            uint2 v = swc4[(r0 + 8) * 8 + ((s * 4 + lk + r0) & 7)];
            A[mt][0] = u.x; A[mt][1] = v.x; A[mt][2] = u.y; A[mt][3] = v.y;
        }
#pragma unroll
        for (int nt = 0; nt < 4; nt++) {
            uint2 f = stg4[(s * 4 + lk) * PAIR_S + pxbase[nt] + koff];
            B4[nt][0] = f.x; B4[nt][1] = f.y;
        }
#pragma unroll
        for (int mt = 0; mt < 4; mt++)
#pragma unroll
            for (int nt = 0; nt < 4; nt++)
                mma16(cacc[mt][nt], A[mt], B4[nt]);
    }
}

template<int OC, int MODE>
__global__ void __launch_bounds__(256, 2) conv_mma_kernel(const float* __restrict__ xin,
                                                          const float* __restrict__ bias) {
    extern __shared__ float sm[];
    uint2*    stg4 = (uint2*)sm;                       // [8][216] u64 groups
    uint32_t* swb  = (uint32_t*)(sm + 8 * PAIR_S * 2); // 4 x 2048 u32

    const float*    x   = (MODE == 0) ? xin : g_xres;
    const uint32_t* wAh = (MODE == 0) ? g_wA1h : g_wA2h;
    float*          y   = (MODE == 0) ? g_xres : g_co;

    const int tid = threadIdx.x;
    const int wid = tid >> 5, lane = tid & 31;
    const int warp_m = wid >> 2, warp_n = wid & 3;
    const int lm = lane >> 2, lk = lane & 3;
    const int b = blockIdx.y;
    const int tile_x = (blockIdx.x % 3) * 32;
    const int tile_y = (blockIdx.x / 3) * 4;

    float cacc[4][4][4];
#pragma unroll
    for (int mt = 0; mt < 4; mt++)
#pragma unroll
        for (int nt = 0; nt < 4; nt++)
#pragma unroll
            for (int i = 0; i < 4; i++) cacc[mt][nt][i] = 0.f;

    int pxbase[4], rowb[4];
#pragma unroll
    for (int nt = 0; nt < 4; nt++) {
        int px = warp_n * 32 + nt * 8 + lm;
        pxbase[nt] = (px >> 5) * 34 + (px & 31);
    }
#pragma unroll
    for (int mt = 0; mt < 4; mt++)
        rowb[mt] = warp_m * 64 + mt * 16 + lm;

    const float* xb = x + (size_t)b * CIN * HWSZ;

    prefetch_w_cp(swb + 0 * 2048, wAh, tid);
    prefetch_w_cp(swb + 1 * 2048, wAh + 2048, tid);

    int np = 2, c = 0;
    for (int icc = 0; icc < 4; icc++) {
        // stage input chunk: 8 groups x 204 positions, 4 channels each -> uint2
        for (int i = tid; i < 8 * 204; i += 256) {
            int g2 = i / 204, rem = i % 204;
            int s = g2 >> 2, lkp = g2 & 3;
            int base = icc * 32 + 16 * s + 2 * lkp;
            int gy = tile_y + rem / 34 - 1, gx = tile_x + rem % 34 - 1;
            float v0 = 0.f, v1 = 0.f, v2 = 0.f, v3 = 0.f;
            if (gy >= 0 && gy < HW && gx >= 0 && gx < HW) {
                const float* p = xb + (size_t)base * HWSZ + gy * HW + gx;
                v0 = p[0]; v1 = p[HWSZ]; v2 = p[8 * HWSZ]; v3 = p[9 * HWSZ];
            }
            uint2 u; u.x = pack_h2(v0, v1); u.y = pack_h2(v2, v3);
            stg4[g2 * PAIR_S + rem] = u;
        }
        CP_WAIT_ALL();
        __syncthreads();

        for (int k0 = 0; k0 < 9; k0 += 2) {
#pragma unroll
            for (int t = 0; t < 2; t++) {
                if (np <= c + 3 && np < 36) {
                    prefetch_w_cp(swb + (np & 3) * 2048, wAh + (size_t)np * 2048, tid);
                    np++;
                }
            }
            {
                const int k = k0;
                conv_tap(cacc, stg4, (const uint2*)(swb + (c & 3) * 2048),
                         (k / 3) * 34 + (k % 3), pxbase, rowb, lk);
            }
            if (k0 < 8) {
                const int k = k0 + 1;
                conv_tap(cacc, stg4, (const uint2*)(swb + ((c + 1) & 3) * 2048),
                         (k / 3) * 34 + (k % 3), pxbase, rowb, lk);
                c += 2;
            } else {
                c += 1;
            }
            CP_WAIT_ALL();
            __syncthreads();
        }
    }

    // epilogue (C frag mapping unchanged by k16)
#pragma unroll
    for (int mt = 0; mt < 4; mt++) {
        int oc0 = warp_m * 64 + mt * 16 + lm;
        int oc1 = oc0 + 8;
#pragma unroll
        for (int nt = 0; nt < 4; nt++) {
            int px0 = warp_n * 32 + nt * 8 + lk * 2;
            int gy = tile_y + (px0 >> 5), gx = tile_x + (px0 & 31);
            if (oc0 < OC) {
                float bz = bias[oc0];
                float2 o = make_float2(cacc[mt][nt][0] + bz, cacc[mt][nt][1] + bz);
                *reinterpret_cast<float2*>(&y[((size_t)(b * OC + oc0)) * HWSZ + gy * HW + gx]) = o;
            }
            if (oc1 < OC) {
                float bz = bias[oc1];
                float2 o = make_float2(cacc[mt][nt][2] + bz, cacc[mt][nt][3] + bz);
                *reinterpret_cast<float2*>(&y[((size_t)(b * OC + oc1)) * HWSZ + gy * HW + gx]) = o;
            }
        }
    }
}

// ---------------- modulated deformable conv (fp16 mma) ----------------
// Thread owns px = tid&127, channel half h = tid>>7 (ics [16h,16h+16) of group g).
// col: [g2(8)][px(COL_S)][lo/hi] u32 pairs -> uint2 B frags, COL_S mod 16 = 4.
#define COL_S 132
#define COLB32 (8 * COL_S * 2)                    // 2112 u32 per buffer
#define DCN_SMEM ((3*2048 + 2*COLB32) * 4)        // 24576 + 16896 = 41472 B

__global__ void __launch_bounds__(256, 2) dcn_mma_kernel(const float* __restrict__ x,
                                                         const float* __restrict__ bias,
                                                         float* __restrict__ y) {
    extern __shared__ float sm[];
    uint32_t* s_w    = (uint32_t*)sm;             // 3 x 2048
    uint32_t* s_colh = s_w + 3 * 2048;            // 2 x 2112

    const int tid = threadIdx.x;
    const int wid = tid >> 5, lane = tid & 31;
    const int warp_m = wid >> 2, warp_n = wid & 3;
    const int lm = lane >> 2, lk = lane & 3;
    const int b = blockIdx.y;
    const int tile_x = (blockIdx.x % 3) * 32;
    const int tile_y = (blockIdx.x / 3) * 4;

    const int px_own = tid & 127;
    const int h      = tid >> 7;                  // channel half
    const int gy_own = tile_y + (px_own >> 5);
    const int gx_own = tile_x + (px_own & 31);

    float cacc[4][4][4];
#pragma unroll
    for (int mt = 0; mt < 4; mt++)
#pragma unroll
        for (int nt = 0; nt < 4; nt++)
#pragma unroll
            for (int i = 0; i < 4; i++) cacc[mt][nt][i] = 0.f;

    int pxidx[4], rowb[4];
#pragma unroll
    for (int nt = 0; nt < 4; nt++)
        pxidx[nt] = warp_n * 32 + nt * 8 + lm;
#pragma unroll
    for (int mt = 0; mt < 4; mt++)
        rowb[mt] = warp_m * 64 + mt * 16 + lm;

    const float* cob = g_co + (size_t)b * OC2 * HWSZ;
    const float* xb  = x    + (size_t)b * CIN * HWSZ;

    auto phaseA_reg = [&](int idx, int4& iv, float4& wv) {
        int g = idx / 9, k = idx - g * 9;
        int c_y = g * 18 + 2 * k;
        const float* basep = cob + gy_own * HW + gx_own;
        float offy = basep[(size_t)c_y * HWSZ];
        float offx = basep[(size_t)(c_y + 1) * HWSZ];
        float mraw = basep[(size_t)(72 + g * 9 + k) * HWSZ];
        float m  = 1.f / (1.f + __expf(-mraw));
        float ys = (float)gy_own + (float)(k / 3 - 1) + offy;
        float xs = (float)gx_own + (float)(k % 3 - 1) + offx;
        float y0f = floorf(ys), x0f = floorf(xs);
        float fy = ys - y0f, fx = xs - x0f;
        int y0 = (int)y0f, x0 = (int)x0f;
        int idxs[4]; float wgts[4];
#pragma unroll
        for (int cnr = 0; cnr < 4; cnr++) {
            int dy = cnr >> 1, dx = cnr & 1;
            int yi = y0 + dy, xi = x0 + dx;
            bool valid = (yi >= 0) && (yi < HW) && (xi >= 0) && (xi < HW);
            float wy = dy ? fy : (1.f - fy);
            float wx = dx ? fx : (1.f - fx);
            int yc = min(max(yi, 0), HW - 1);
            int xc = min(max(xi, 0), HW - 1);
            idxs[cnr] = yc * HW + xc;
            wgts[cnr] = valid ? (wy * wx * m) : 0.f;
        }
        iv = make_int4(idxs[0], idxs[1], idxs[2], idxs[3]);
        wv = make_float4(wgts[0], wgts[1], wgts[2], wgts[3]);
    };

    // quarter q: channels 16h + 4q .. +3
    auto issue_loads = [&](int g, int q, const int4 iv, float vals[16]) {
        const float* xg = xb + (size_t)(g * 32 + 16 * h) * HWSZ;
#pragma unroll
        for (int jj = 0; jj < 4; jj++) {
            const float* xp = xg + (size_t)(q * 4 + jj) * HWSZ;
            vals[jj * 4 + 0] = __ldg(xp + iv.x);
            vals[jj * 4 + 1] = __ldg(xp + iv.y);
            vals[jj * 4 + 2] = __ldg(xp + iv.z);
            vals[jj * 4 + 3] = __ldg(xp + iv.w);
        }
    };
    // combine: q<2 saves lo-halves; q>=2 emits full uint2 stores
    auto combine = [&](int it1, int q, const float4 wv, const float vals[16],
                       uint32_t save[2][2]) {
        float v[4];
#pragma unroll
        for (int jj = 0; jj < 4; jj++)
            v[jj] = wv.x * vals[jj * 4 + 0] + wv.y * vals[jj * 4 + 1]
                  + wv.z * vals[jj * 4 + 2] + wv.w * vals[jj * 4 + 3];
        uint32_t u01 = pack_h2(v[0], v[1]);
        uint32_t u23 = pack_h2(v[2], v[3]);
        if (q < 2) {
            save[q][0] = u01; save[q][1] = u23;
        } else {
            uint2* col2 = (uint2*)(s_colh + (it1 & 1) * COLB32);
            int g2a = 4 * h + 2 * (q - 2);
            col2[g2a * COL_S + px_own]       = make_uint2(save[q - 2][0], u01);
            col2[(g2a + 1) * COL_S + px_own] = make_uint2(save[q - 2][1], u23);
        }
    };

    auto do_mma_s = [&](int it, int wslot, int s) {
        const uint2* swc4 = (const uint2*)(s_w + wslot * 2048);
        const uint2* col2 = (const uint2*)(s_colh + (it & 1) * COLB32);
        uint32_t A[4][4], B4[4][2];
#pragma unroll
        for (int mt = 0; mt < 4; mt++) {
            int r0 = rowb[mt];
            uint2 u = swc4[r0 * 8 + ((s * 4 + lk + r0) & 7)];
            uint2 v = swc4[(r0 + 8) * 8 + ((s * 4 + lk + r0) & 7)];
            A[mt][0] = u.x; A[mt][1] = v.x; A[mt][2] = u.y; A[mt][3] = v.y;
        }
#pragma unroll
        for (int nt = 0; nt < 4; nt++) {
            uint2 f = col2[(s * 4 + lk) * COL_S + pxidx[nt]];
            B4[nt][0] = f.x; B4[nt][1] = f.y;
        }
#pragma unroll
        for (int mt = 0; mt < 4; mt++)
#pragma unroll
            for (int nt = 0; nt < 4; nt++)
                mma16(cacc[mt][nt], A[mt], B4[nt]);
    };

    // ---- prologue ----
    prefetch_w_cp(s_w + 0 * 2048, g_wdh, tid);
    prefetch_w_cp(s_w + 1 * 2048, g_wdh + 2048, tid);
    {
        int4 iv; float4 wv;
        phaseA_reg(0, iv, wv);
        float vals[16]; uint32_t save[2][2];
#pragma unroll
        for (int q = 0; q < 4; q++) { issue_loads(0, q, iv, vals); combine(0, q, wv, vals, save); }
    }

    // ---- main pipeline: 1 barrier per tap; 2 MMA s-steps interleaved with gather ----
    int wslot = 0, pslot = 2;
    for (int it = 0; it < 36; it++) {
        int4 ivn; float4 wvn;
        if (it < 35) phaseA_reg(it + 1, ivn, wvn);
        CP_WAIT_ALL();
        __syncthreads();
        if (it < 34) prefetch_w_cp(s_w + pslot * 2048, g_wdh + (size_t)(it + 2) * 2048, tid);
        if (it < 35) {
            int gn = (it + 1) / 9;
            float vals[16]; uint32_t save[2][2];
            issue_loads(gn, 0, ivn, vals);
            do_mma_s(it, wslot, 0);
            combine(it + 1, 0, wvn, vals, save);
            issue_loads(gn, 1, ivn, vals);
            combine(it + 1, 1, wvn, vals, save);
            issue_loads(gn, 2, ivn, vals);
            do_mma_s(it, wslot, 1);
            combine(it + 1, 2, wvn, vals, save);
            issue_loads(gn, 3, ivn, vals);
            combine(it + 1, 3, wvn, vals, save);
        } else {
            do_mma_s(it, wslot, 0);
            do_mma_s(it, wslot, 1);
        }
        wslot = (wslot == 2) ? 0 : wslot + 1;
        pslot = (pslot == 2) ? 0 : pslot + 1;
    }

    // epilogue
#pragma unroll
    for (int mt = 0; mt < 4; mt++) {
        int oc0 = warp_m * 64 + mt * 16 + lm;
        int oc1 = oc0 + 8;
        float bz0 = bias[oc0], bz1 = bias[oc1];
#pragma unroll
        for (int nt = 0; nt < 4; nt++) {
            int px0 = warp_n * 32 + nt * 8 + lk * 2;
            int gy = tile_y + (px0 >> 5), gx = tile_x + (px0 & 31);
            *reinterpret_cast<float2*>(&y[((size_t)(b * OC1 + oc0)) * HWSZ + gy * HW + gx]) =
                make_float2(cacc[mt][nt][0] + bz0, cacc[mt][nt][1] + bz0);
            *reinterpret_cast<float2*>(&y[((size_t)(b * OC1 + oc1)) * HWSZ + gy * HW + gx]) =
                make_float2(cacc[mt][nt][2] + bz1, cacc[mt][nt][3] + bz1);
        }
    }
}

// ---------------- launch ----------------
extern "C" void kernel_launch(void* const* d_in, const int* in_sizes, int n_in,
                              void* d_out, int out_size) {
    (void)in_sizes; (void)n_in; (void)out_size;
    const float* x_vq  = (const float*)d_in[0];
    const float* w_off = (const float*)d_in[1];
    const float* b_off = (const float*)d_in[2];
    const float* w_co  = (const float*)d_in[3];
    const float* b_co  = (const float*)d_in[4];
    const float* w_dcn = (const float*)d_in[5];
    const float* b_dcn = (const float*)d_in[6];
    float* out = (float*)d_out;

    cudaFuncSetAttribute(conv_mma_kernel<OC1, 0>, cudaFuncAttributeMaxDynamicSharedMemorySize, CONV_SMEM);
    cudaFuncSetAttribute(conv_mma_kernel<OC2, 1>, cudaFuncAttributeMaxDynamicSharedMemorySize, CONV_SMEM);
    cudaFuncSetAttribute(dcn_mma_kernel, cudaFuncAttributeMaxDynamicSharedMemorySize, DCN_SMEM);

    prep_wh_kernel<<<288, 256>>>(w_off, OC1, 0);
    prep_wh_kernel<<<288, 256>>>(w_co,  OC2, 1);
    prep_wh_kernel<<<288, 256>>>(w_dcn, OC1, 2);

    dim3 cgrid(72, BATCH);   // 3x24 tiles of 32x4 px, 128 oc per CTA
    conv_mma_kernel<OC1, 0><<<cgrid, 256, CONV_SMEM>>>(x_vq, b_off);
    conv_mma_kernel<OC2, 1><<<cgrid, 256, CONV_SMEM>>>(nullptr, b_co);

    dim3 dgrid(72, BATCH);
    dcn_mma_kernel<<<dgrid, 256, DCN_SMEM>>>(x_vq, b_dcn, out);
}